// round 12
// baseline (speedup 1.0000x reference)
#include <cuda_runtime.h>
#include <cuda_bf16.h>
#include <cuda_fp16.h>
#include <math.h>
#include <stdint.h>

#define NN   100000
#define EE   1600000
#define GG   512
#define IN_C 96
#define HID  128
#define NCLS 100
#define SCAN_BLOCKS 98   // ceil(100000/1024)
#define ETILES 4         // edge tiles per block (512 edges) — measured best

// ---------------- scratch (device globals; no allocation) ----------------
__device__ float  d_ew[EE];
__device__ int    d_pos[EE];
__device__ int    d_cnt[NN];
__device__ int    d_rowptr[NN + 1];
__device__ int    d_bsum[SCAN_BLOCKS];
__device__ int    d_boff[SCAN_BLOCKS];
__device__ float2 d_adj[EE];            // packed (src as int bits, norm)
__device__ float  d_deg[NN];
__device__ float  d_dis[NN];
__device__ __half d_hwh[(size_t)NN * HID];        // GEMM output (gather source)
__device__ __half d_hall[4 * (size_t)NN * HID];   // per-layer hidden activations
__device__ float  d_res0[(size_t)NN * HID];
__device__ int    d_gstart[GG + 1];
__device__ float  d_gmean[GG * HID];
__device__ float  d_gmaxv[GG * HID];
// pre-split weights, n-major [128 n][128 k] bf16, hi and lo parts, 5 matrices
__device__ __nv_bfloat16 d_Bh[5 * 128 * 128];
__device__ __nv_bfloat16 d_Bl[5 * 128 * 128];
// edge-MLP W1 pre-packed, n-major [128 n][16 k]
__device__ __nv_bfloat16 d_EB1[128 * 16];
__device__ __nv_bfloat16 d_EB2[128 * 16];

// ---------------- init ----------------
__global__ void init_k() {
    int i = blockIdx.x * blockDim.x + threadIdx.x;
    if (i < NN) { d_deg[i] = 1.0f; d_cnt[i] = 0; }
    if (i <= GG) d_gstart[i] = NN;
}

// ---------------- mma helper ----------------
__device__ __forceinline__ void mma16816(float* c, const uint32_t* a, const uint32_t* b) {
    asm volatile(
        "mma.sync.aligned.m16n8k16.row.col.f32.bf16.bf16.f32 "
        "{%0,%1,%2,%3}, {%4,%5,%6,%7}, {%8,%9}, {%0,%1,%2,%3};"
        : "+f"(c[0]), "+f"(c[1]), "+f"(c[2]), "+f"(c[3])
        : "r"(a[0]), "r"(a[1]), "r"(a[2]), "r"(a[3]), "r"(b[0]), "r"(b[1]));
}

__device__ __forceinline__ void split_bf16(float v, __nv_bfloat16& h, __nv_bfloat16& l) {
    h = __float2bfloat16_rn(v);
    l = __float2bfloat16_rn(v - __bfloat162float(h));
}

// ---------------- edge W1 prep ----------------
__global__ __launch_bounds__(128) void prep_e_k(const float* __restrict__ W1) {
    int n = threadIdx.x;
    __nv_bfloat16 z = __float2bfloat16_rn(0.f);
    for (int k = 0; k < 8; k++) {
        float v = W1[k * 128 + n];
        __nv_bfloat16 h, l;
        split_bf16(v, h, l);
        d_EB1[n * 16 + k] = h;
        d_EB1[n * 16 + 8 + k] = h;
        d_EB2[n * 16 + k] = l;
        d_EB2[n * 16 + 8 + k] = z;
    }
}

// ---------------- tensor-core edge MLP + softplus + deg/count (fused, multi-tile) ----------------
#define EPITCH 24
__global__ __launch_bounds__(256) void edge_mma_k(
    const float* __restrict__ ea, const float* __restrict__ b1,
    const float* __restrict__ W2, const float* __restrict__ b2v,
    const int* __restrict__ col)
{
    __shared__ __nv_bfloat16 As[128 * EPITCH];
    __shared__ __nv_bfloat16 B1s[128 * EPITCH];
    __shared__ __nv_bfloat16 B2s[128 * EPITCH];
    __shared__ float b1s[128];
    __shared__ float W2s[128];
    __shared__ float part[128][2];

    int tid = threadIdx.x;
    int eb = blockIdx.x * (128 * ETILES);

    if (tid < 128) { b1s[tid] = b1[tid]; W2s[tid] = W2[tid]; }

    for (int i = tid; i < 128 * 16; i += 256) {
        int n = i >> 4, k = i & 15;
        B1s[n * EPITCH + k] = d_EB1[i];
        B2s[n * EPITCH + k] = d_EB2[i];
    }
    __syncthreads();

    int wid = tid >> 5, lane = tid & 31;
    int g = lane >> 2, tig = lane & 3;
    int wr = (wid & 3) * 32;
    int wc = (wid >> 2) * 64;
    int eS = tid >> 1, half = tid & 1;

    uint32_t b1f[8][2], b2f[8][2];
    #pragma unroll
    for (int nt = 0; nt < 8; nt++) {
        const __nv_bfloat16* nb1 = B1s + (wc + nt * 8 + g) * EPITCH;
        const __nv_bfloat16* nb2 = B2s + (wc + nt * 8 + g) * EPITCH;
        b1f[nt][0] = *(const uint32_t*)(nb1 + 2 * tig);
        b1f[nt][1] = *(const uint32_t*)(nb1 + 8 + 2 * tig);
        b2f[nt][0] = *(const uint32_t*)(nb2 + 2 * tig);
        b2f[nt][1] = *(const uint32_t*)(nb2 + 8 + 2 * tig);
    }

    for (int t = 0; t < ETILES; t++) {
        int e0 = eb + t * 128;
        {
            float4 v = *(const float4*)(ea + (size_t)(e0 + eS) * 8 + half * 4);
            __nv_bfloat16 h0, l0, h1, l1, h2, l2, h3, l3;
            split_bf16(v.x, h0, l0); split_bf16(v.y, h1, l1);
            split_bf16(v.z, h2, l2); split_bf16(v.w, h3, l3);
            __nv_bfloat16* ah = As + eS * EPITCH + half * 4;
            ah[0] = h0; ah[1] = h1; ah[2] = h2; ah[3] = h3;
            ah[8] = l0; ah[9] = l1; ah[10] = l2; ah[11] = l3;
        }
        __syncthreads();

        uint32_t af[2][4];
        #pragma unroll
        for (int mt = 0; mt < 2; mt++) {
            const __nv_bfloat16* base = As + (wr + mt * 16) * EPITCH;
            af[mt][0] = *(const uint32_t*)(base + g * EPITCH + 2 * tig);
            af[mt][1] = *(const uint32_t*)(base + (g + 8) * EPITCH + 2 * tig);
            af[mt][2] = *(const uint32_t*)(base + g * EPITCH + 8 + 2 * tig);
            af[mt][3] = *(const uint32_t*)(base + (g + 8) * EPITCH + 8 + 2 * tig);
        }

        float s0[2] = {0.f, 0.f}, s8[2] = {0.f, 0.f};
        #pragma unroll
        for (int nt = 0; nt < 8; nt++) {
            float c0[4] = {0.f, 0.f, 0.f, 0.f};
            float c1[4] = {0.f, 0.f, 0.f, 0.f};
            mma16816(c0, af[0], b1f[nt]);
            mma16816(c1, af[1], b1f[nt]);
            mma16816(c0, af[0], b2f[nt]);
            mma16816(c1, af[1], b2f[nt]);
            int c = wc + nt * 8 + 2 * tig;
            float w0 = W2s[c], w1 = W2s[c + 1];
            float bb0 = b1s[c], bb1 = b1s[c + 1];
            s0[0] = fmaf(fmaxf(c0[0] + bb0, 0.f), w0, s0[0]);
            s0[0] = fmaf(fmaxf(c0[1] + bb1, 0.f), w1, s0[0]);
            s8[0] = fmaf(fmaxf(c0[2] + bb0, 0.f), w0, s8[0]);
            s8[0] = fmaf(fmaxf(c0[3] + bb1, 0.f), w1, s8[0]);
            s0[1] = fmaf(fmaxf(c1[0] + bb0, 0.f), w0, s0[1]);
            s0[1] = fmaf(fmaxf(c1[1] + bb1, 0.f), w1, s0[1]);
            s8[1] = fmaf(fmaxf(c1[2] + bb0, 0.f), w0, s8[1]);
            s8[1] = fmaf(fmaxf(c1[3] + bb1, 0.f), w1, s8[1]);
        }
        #pragma unroll
        for (int mt = 0; mt < 2; mt++) {
            float v0 = s0[mt], v8 = s8[mt];
            v0 += __shfl_xor_sync(0xffffffffu, v0, 1);
            v0 += __shfl_xor_sync(0xffffffffu, v0, 2);
            v8 += __shfl_xor_sync(0xffffffffu, v8, 1);
            v8 += __shfl_xor_sync(0xffffffffu, v8, 2);
            if (tig == 0) {
                int wn = wid >> 2;
                part[wr + mt * 16 + g][wn] = v0;
                part[wr + mt * 16 + g + 8][wn] = v8;
            }
        }
        __syncthreads();

        if (tid < 128) {
            int e = e0 + tid;
            float x = part[tid][0] + part[tid][1] + b2v[0];
            float sp = (x > 15.f) ? x : log1pf(expf(x));
            float ew = sp + 1e-4f;
            d_ew[e] = ew;
            int c = col[e];
            d_pos[e] = atomicAdd(&d_cnt[c], 1);
            atomicAdd(&d_deg[c], ew);
        }
        __syncthreads();
    }
}

__global__ void dis_k() {
    int i = blockIdx.x * blockDim.x + threadIdx.x;
    if (i < NN) d_dis[i] = rsqrtf(d_deg[i]);
}

// ---------------- hierarchical scan ----------------
__global__ __launch_bounds__(1024) void scan1_k() {
    __shared__ int wsum[32];
    int tid = threadIdx.x, lane = tid & 31, wid = tid >> 5;
    int i = blockIdx.x * 1024 + tid;
    int v = (i < NN) ? d_cnt[i] : 0;
    int s = v;
    #pragma unroll
    for (int o = 1; o < 32; o <<= 1) {
        int t = __shfl_up_sync(0xffffffffu, s, o);
        if (lane >= o) s += t;
    }
    if (lane == 31) wsum[wid] = s;
    __syncthreads();
    if (wid == 0) {
        int ws = wsum[lane];
        #pragma unroll
        for (int o = 1; o < 32; o <<= 1) {
            int t = __shfl_up_sync(0xffffffffu, ws, o);
            if (lane >= o) ws += t;
        }
        wsum[lane] = ws;
    }
    __syncthreads();
    int incl = s + ((wid > 0) ? wsum[wid - 1] : 0);
    if (i < NN) d_rowptr[i + 1] = incl;
    if (tid == 1023) d_bsum[blockIdx.x] = incl;
}

__global__ __launch_bounds__(128) void scan2_k() {
    int tid = threadIdx.x, lane = tid & 31, wid = tid >> 5;
    __shared__ int wsum[4];
    int v = (tid < SCAN_BLOCKS) ? d_bsum[tid] : 0;
    int s = v;
    #pragma unroll
    for (int o = 1; o < 32; o <<= 1) {
        int t = __shfl_up_sync(0xffffffffu, s, o);
        if (lane >= o) s += t;
    }
    if (lane == 31) wsum[wid] = s;
    __syncthreads();
    int add = 0;
    for (int w = 0; w < 4; w++) if (w < wid) add += wsum[w];
    if (tid < SCAN_BLOCKS) d_boff[tid] = s + add - v;
}

__global__ __launch_bounds__(1024) void scan3_k() {
    int i = blockIdx.x * 1024 + threadIdx.x;
    if (i < NN) d_rowptr[i + 1] += d_boff[blockIdx.x];
    if (i == 0) d_rowptr[0] = 0;
}

// ---------------- fill CSR (packed src+norm) ----------------
__global__ void fill_k(const int* __restrict__ row, const int* __restrict__ col) {
    int e = blockIdx.x * blockDim.x + threadIdx.x;
    if (e >= EE) return;
    int r = row[e], c = col[e];
    int j = d_rowptr[c] + d_pos[e];
    float2 v;
    v.x = __int_as_float(r);
    v.y = d_dis[r] * d_ew[e] * d_dis[c];
    d_adj[j] = v;
}

// ---------------- weight prep ----------------
__global__ __launch_bounds__(128) void prep_k(
    const float* __restrict__ resW, const float* __restrict__ W0,
    const float* __restrict__ W1, const float* __restrict__ W2,
    const float* __restrict__ W3)
{
    int m = blockIdx.x, n = threadIdx.x;
    const float* W; int K;
    switch (m) {
        case 0: W = resW; K = 96; break;
        case 1: W = W0;   K = 96; break;
        case 2: W = W1;   K = 128; break;
        case 3: W = W2;   K = 128; break;
        default: W = W3;  K = 128; break;
    }
    __nv_bfloat16* bh = d_Bh + (size_t)m * 16384 + (size_t)n * 128;
    __nv_bfloat16* bl = d_Bl + (size_t)m * 16384 + (size_t)n * 128;
    for (int k = 0; k < 128; k++) {
        float v = (k < K) ? W[(size_t)k * HID + n] : 0.f;
        __nv_bfloat16 h, l;
        split_bf16(v, h, l);
        bh[k] = h;
        bl[k] = l;
    }
}

// ---------------- HMMA bf16 split GEMM ----------------
#define PITCH 136
#define BUFSZ (128 * PITCH)
#define SMEM_GEMM (4 * BUFSZ * 2)

// asel: -1 -> Ain fp32 (lda cols) ; 0..3 -> d_hall[asel] fp16 (128 cols)
// pass 1: mat/osel ; pass 2 optional (mat2 < 0 skip), reuses staged A
// osel: 0 -> d_hwh (half), 1 -> d_res0 (f32)
__global__ __launch_bounds__(256) void mma_gemm_k(
    const float* __restrict__ Ain, int asel, int osel, int mat,
    int lda, const float* __restrict__ bias,
    int osel2, int mat2, const float* __restrict__ bias2)
{
    extern __shared__ __nv_bfloat16 sm[];
    __nv_bfloat16* AhiS = sm;
    __nv_bfloat16* AloS = sm + BUFSZ;
    __nv_bfloat16* BhS  = sm + 2 * BUFSZ;
    __nv_bfloat16* BlS  = sm + 3 * BUFSZ;
    __shared__ float biasS[128];

    int tid = threadIdx.x;
    int r0 = blockIdx.x * 128;

    // stage A (fp32 or fp16 -> hi/lo bf16) once
    {
        const __half* A16 = (asel >= 0) ? (d_hall + (size_t)asel * NN * HID) : nullptr;
        int rr = tid >> 5;
        int cc = (tid & 31) * 4;
        #pragma unroll 4
        for (int it = 0; it < 16; it++) {
            int r = it * 8 + rr;
            int R = r0 + r;
            float4 v = make_float4(0.f, 0.f, 0.f, 0.f);
            if (asel >= 0) {
                if (R < NN) {
                    uint2 raw = *(const uint2*)(A16 + (size_t)R * HID + cc);
                    float2 f0 = __half22float2(*(__half2*)&raw.x);
                    float2 f1 = __half22float2(*(__half2*)&raw.y);
                    v = make_float4(f0.x, f0.y, f1.x, f1.y);
                }
            } else {
                if (R < NN && cc < lda)
                    v = *(const float4*)(Ain + (size_t)R * lda + cc);
            }
            __nv_bfloat16 h0, l0, h1, l1, h2, l2, h3, l3;
            split_bf16(v.x, h0, l0); split_bf16(v.y, h1, l1);
            split_bf16(v.z, h2, l2); split_bf16(v.w, h3, l3);
            uint2 ph, pl;
            ph.x = ((uint32_t)__bfloat16_as_ushort(h1) << 16) | __bfloat16_as_ushort(h0);
            ph.y = ((uint32_t)__bfloat16_as_ushort(h3) << 16) | __bfloat16_as_ushort(h2);
            pl.x = ((uint32_t)__bfloat16_as_ushort(l1) << 16) | __bfloat16_as_ushort(l0);
            pl.y = ((uint32_t)__bfloat16_as_ushort(l3) << 16) | __bfloat16_as_ushort(l2);
            *(uint2*)(AhiS + r * PITCH + cc) = ph;
            *(uint2*)(AloS + r * PITCH + cc) = pl;
        }
    }

    int wid = tid >> 5, lane = tid & 31;
    int g = lane >> 2, tig = lane & 3;
    int wr = (wid & 3) * 32;
    int wc = (wid >> 2) * 64;

    int curMat = mat, curOsel = osel;
    const float* curBias = bias;

    for (int pass = 0; pass < 2; pass++) {
        if (pass == 1) {
            if (mat2 < 0) break;
            curMat = mat2; curOsel = osel2; curBias = bias2;
            __syncthreads();
        }
        {
            int rr = tid >> 5;
            int cc = (tid & 31) * 4;
            const __nv_bfloat16* gh = d_Bh + (size_t)curMat * 16384;
            const __nv_bfloat16* gl = d_Bl + (size_t)curMat * 16384;
            #pragma unroll 4
            for (int it = 0; it < 16; it++) {
                int n = it * 8 + rr;
                *(uint2*)(BhS + n * PITCH + cc) = *(const uint2*)(gh + n * 128 + cc);
                *(uint2*)(BlS + n * PITCH + cc) = *(const uint2*)(gl + n * 128 + cc);
            }
        }
        if (tid < 128) biasS[tid] = curBias ? curBias[tid] : 0.f;
        __syncthreads();

        float cacc[2][8][4];
        #pragma unroll
        for (int mt = 0; mt < 2; mt++)
            #pragma unroll
            for (int nt = 0; nt < 8; nt++)
                #pragma unroll
                for (int q = 0; q < 4; q++) cacc[mt][nt][q] = 0.f;

        #pragma unroll
        for (int p = 0; p < 3; p++) {
            const __nv_bfloat16* As = (p == 1) ? AloS : AhiS;
            const __nv_bfloat16* Bs = (p == 2) ? BlS : BhS;
            #pragma unroll
            for (int ks = 0; ks < 8; ks++) {
                int k0 = ks * 16;
                uint32_t af[2][4];
                #pragma unroll
                for (int mt = 0; mt < 2; mt++) {
                    const __nv_bfloat16* base = As + (wr + mt * 16) * PITCH + k0;
                    af[mt][0] = *(const uint32_t*)(base + g * PITCH + 2 * tig);
                    af[mt][1] = *(const uint32_t*)(base + (g + 8) * PITCH + 2 * tig);
                    af[mt][2] = *(const uint32_t*)(base + g * PITCH + 8 + 2 * tig);
                    af[mt][3] = *(const uint32_t*)(base + (g + 8) * PITCH + 8 + 2 * tig);
                }
                #pragma unroll
                for (int nt = 0; nt < 8; nt++) {
                    uint32_t bf[2];
                    const __nv_bfloat16* nb = Bs + (wc + nt * 8 + g) * PITCH + k0;
                    bf[0] = *(const uint32_t*)(nb + 2 * tig);
                    bf[1] = *(const uint32_t*)(nb + 8 + 2 * tig);
                    mma16816(cacc[0][nt], af[0], bf);
                    mma16816(cacc[1][nt], af[1], bf);
                }
            }
        }

        #pragma unroll
        for (int mt = 0; mt < 2; mt++) {
            int row = r0 + wr + mt * 16 + g;
            #pragma unroll
            for (int nt = 0; nt < 8; nt++) {
                int col = wc + nt * 8 + 2 * tig;
                float b0 = biasS[col], b1 = biasS[col + 1];
                float v00 = cacc[mt][nt][0] + b0, v01 = cacc[mt][nt][1] + b1;
                float v10 = cacc[mt][nt][2] + b0, v11 = cacc[mt][nt][3] + b1;
                if (curOsel == 1) {
                    if (row < NN)
                        *(float2*)(d_res0 + (size_t)row * HID + col) = make_float2(v00, v01);
                    if (row + 8 < NN)
                        *(float2*)(d_res0 + (size_t)(row + 8) * HID + col) = make_float2(v10, v11);
                } else {
                    if (row < NN)
                        *(__half2*)(d_hwh + (size_t)row * HID + col) =
                            __floats2half2_rn(v00, v01);
                    if (row + 8 < NN)
                        *(__half2*)(d_hwh + (size_t)(row + 8) * HID + col) =
                            __floats2half2_rn(v10, v11);
                }
            }
        }
    }
}

// ---------------- fused aggregate + bias + LN + residual + relu -> fp16 h ----------------
// 2 nodes per warp: 16 lanes per node, each lane holds 8 channels (uint4 = 16B).
__device__ __forceinline__ void acc_edge8(float* acc, float w, uint4 raw) {
    float2 f0 = __half22float2(*(__half2*)&raw.x);
    float2 f1 = __half22float2(*(__half2*)&raw.y);
    float2 f2 = __half22float2(*(__half2*)&raw.z);
    float2 f3 = __half22float2(*(__half2*)&raw.w);
    acc[0] = fmaf(w, f0.x, acc[0]);
    acc[1] = fmaf(w, f0.y, acc[1]);
    acc[2] = fmaf(w, f1.x, acc[2]);
    acc[3] = fmaf(w, f1.y, acc[3]);
    acc[4] = fmaf(w, f2.x, acc[4]);
    acc[5] = fmaf(w, f2.y, acc[5]);
    acc[6] = fmaf(w, f3.x, acc[6]);
    acc[7] = fmaf(w, f3.y, acc[7]);
}

// rsel: -1 -> d_res0 (fp32), 0..3 -> d_hall[rsel] fp16 ; hsel: output layer index
__global__ __launch_bounds__(256) void agg_ln_k(
    const float* __restrict__ cb, const float* __restrict__ gam,
    const float* __restrict__ bet, int rsel, int hsel)
{
    int lane = threadIdx.x & 31;
    int sub = lane >> 4;        // which node of the pair
    int l16 = lane & 15;
    int n = ((blockIdx.x * 256 + threadIdx.x) >> 5) * 2 + sub;
    if (n >= NN) return;
    const uint4* hw4 = (const uint4*)d_hwh;   // row = 16 uint4

    float acc[8];
    {
        float4 c0 = ((const float4*)cb)[l16 * 2];
        float4 c1 = ((const float4*)cb)[l16 * 2 + 1];
        acc[0] = c0.x; acc[1] = c0.y; acc[2] = c0.z; acc[3] = c0.w;
        acc[4] = c1.x; acc[5] = c1.y; acc[6] = c1.z; acc[7] = c1.w;
    }
    float dn = d_dis[n];
    float sn = dn * dn;
    acc_edge8(acc, sn, hw4[(size_t)n * 16 + l16]);

    int jb = d_rowptr[n], je = d_rowptr[n + 1];
    int j = jb;
    for (; j + 4 <= je; j += 4) {
        float2 a0 = d_adj[j];
        float2 a1 = d_adj[j + 1];
        float2 a2 = d_adj[j + 2];
        float2 a3 = d_adj[j + 3];
        uint4 r0 = hw4[(size_t)__float_as_int(a0.x) * 16 + l16];
        uint4 r1 = hw4[(size_t)__float_as_int(a1.x) * 16 + l16];
        uint4 r2 = hw4[(size_t)__float_as_int(a2.x) * 16 + l16];
        uint4 r3 = hw4[(size_t)__float_as_int(a3.x) * 16 + l16];
        acc_edge8(acc, a0.y, r0);
        acc_edge8(acc, a1.y, r1);
        acc_edge8(acc, a2.y, r2);
        acc_edge8(acc, a3.y, r3);
    }
    for (; j < je; j++) {
        float2 a = d_adj[j];
        acc_edge8(acc, a.y, hw4[(size_t)__float_as_int(a.x) * 16 + l16]);
    }

    // LayerNorm over 128 channels = 8 per lane x 16 lanes
    float ss = acc[0] + acc[1] + acc[2] + acc[3] + acc[4] + acc[5] + acc[6] + acc[7];
    #pragma unroll
    for (int o = 8; o > 0; o >>= 1) ss += __shfl_xor_sync(0xffffffffu, ss, o);
    float mu = ss * (1.f / 128.f);
    float dx[8];
    float q = 0.f;
    #pragma unroll
    for (int i = 0; i < 8; i++) { dx[i] = acc[i] - mu; q = fmaf(dx[i], dx[i], q); }
    #pragma unroll
    for (int o = 8; o > 0; o >>= 1) q += __shfl_xor_sync(0xffffffffu, q, o);
    float rstd = rsqrtf(q * (1.f / 128.f) + 1e-5f);

    float4 g0 = ((const float4*)gam)[l16 * 2];
    float4 g1 = ((const float4*)gam)[l16 * 2 + 1];
    float4 b0 = ((const float4*)bet)[l16 * 2];
    float4 b1 = ((const float4*)bet)[l16 * 2 + 1];
    float gv[8] = {g0.x, g0.y, g0.z, g0.w, g1.x, g1.y, g1.z, g1.w};
    float bv[8] = {b0.x, b0.y, b0.z, b0.w, b1.x, b1.y, b1.z, b1.w};
    float rv[8];
    if (rsel < 0) {
        float4 r0 = ((const float4*)d_res0)[(size_t)n * 32 + l16 * 2];
        float4 r1 = ((const float4*)d_res0)[(size_t)n * 32 + l16 * 2 + 1];
        rv[0] = r0.x; rv[1] = r0.y; rv[2] = r0.z; rv[3] = r0.w;
        rv[4] = r1.x; rv[5] = r1.y; rv[6] = r1.z; rv[7] = r1.w;
    } else {
        const __half* rp = d_hall + (size_t)rsel * NN * HID;
        uint4 raw = *(const uint4*)(rp + (size_t)n * HID + l16 * 8);
        float2 f0 = __half22float2(*(__half2*)&raw.x);
        float2 f1 = __half22float2(*(__half2*)&raw.y);
        float2 f2 = __half22float2(*(__half2*)&raw.z);
        float2 f3 = __half22float2(*(__half2*)&raw.w);
        rv[0] = f0.x; rv[1] = f0.y; rv[2] = f1.x; rv[3] = f1.y;
        rv[4] = f2.x; rv[5] = f2.y; rv[6] = f3.x; rv[7] = f3.y;
    }

    float h[8];
    #pragma unroll
    for (int i = 0; i < 8; i++)
        h[i] = fmaxf(fmaf(gv[i], dx[i] * rstd, bv[i]) + rv[i], 0.f);

    __half* hb = d_hall + (size_t)hsel * NN * HID;
    uint4 pk;
    *(__half2*)&pk.x = __floats2half2_rn(h[0], h[1]);
    *(__half2*)&pk.y = __floats2half2_rn(h[2], h[3]);
    *(__half2*)&pk.z = __floats2half2_rn(h[4], h[5]);
    *(__half2*)&pk.w = __floats2half2_rn(h[6], h[7]);
    *(uint4*)(hb + (size_t)n * HID + l16 * 8) = pk;
}

// ---------------- graph segment boundaries ----------------
__global__ void mark_k(const int* __restrict__ batch) {
    int n = blockIdx.x * blockDim.x + threadIdx.x;
    if (n >= NN) return;
    int b = batch[n];
    if (n == 0 || batch[n - 1] != b) atomicMin(&d_gstart[b], n);
}

__global__ __launch_bounds__(512) void fix_k() {
    __shared__ int s[520];
    int t = threadIdx.x;
    s[t] = d_gstart[t];
    if (t == 0) s[GG] = NN;
    __syncthreads();
    for (int o = 1; o <= GG; o <<= 1) {
        int v = s[t];
        int u = (t + o <= GG) ? s[t + o] : NN;
        __syncthreads();
        s[t] = min(v, u);
        __syncthreads();
    }
    d_gstart[t] = s[t];
}

// ---------------- pooling: mean+max of (h0+h1+h2+h3)/4 over each graph ----------------
__global__ __launch_bounds__(128) void pool_k() {
    int g = blockIdx.x, c = threadIdx.x;
    int s = d_gstart[g], e = d_gstart[g + 1];
    const __half* h0 = d_hall;
    const __half* h1 = d_hall + (size_t)NN * HID;
    const __half* h2 = d_hall + 2 * (size_t)NN * HID;
    const __half* h3 = d_hall + 3 * (size_t)NN * HID;
    float sum = 0.f, mx = 0.f;
    for (int n = s; n < e; n++) {
        size_t off = (size_t)n * HID + c;
        float v = (__half2float(h0[off]) + __half2float(h1[off])
                 + __half2float(h2[off]) + __half2float(h3[off])) * 0.25f;
        sum += v;
        mx = fmaxf(mx, v);
    }
    int cnt = e - s;
    d_gmean[g * HID + c] = sum / (float)max(cnt, 1);
    d_gmaxv[g * HID + c] = mx;
}

// ---------------- head ----------------
__global__ __launch_bounds__(128) void head_k(
    const float* __restrict__ hW1, const float* __restrict__ hb1,
    const float* __restrict__ hW2, const float* __restrict__ hb2,
    float* __restrict__ out)
{
    __shared__ float gf[256];
    __shared__ float h1s[128];
    int g = blockIdx.x, t = threadIdx.x;
    gf[t] = d_gmean[g * HID + t];
    gf[128 + t] = d_gmaxv[g * HID + t];
    __syncthreads();
    float acc = hb1[t];
    #pragma unroll 8
    for (int k = 0; k < 256; k++) acc = fmaf(gf[k], hW1[k * HID + t], acc);
    h1s[t] = fmaxf(acc, 0.f);
    __syncthreads();
    if (t < NCLS) {
        float o = hb2[t];
        #pragma unroll 8
        for (int k = 0; k < 128; k++) o = fmaf(h1s[k], hW2[k * NCLS + t], o);
        out[g * NCLS + t] = o;
    }
}

// ---------------- launcher ----------------
extern "C" void kernel_launch(void* const* d_in, const int* in_sizes, int n_in,
                              void* d_out, int out_size) {
    const float* x     = (const float*)d_in[0];
    const int*   ei    = (const int*)d_in[1];
    const int*   batch = (const int*)d_in[2];
    const float* ea    = (const float*)d_in[3];
    const float* eeW1  = (const float*)d_in[4];
    const float* eeb1  = (const float*)d_in[5];
    const float* eeW2  = (const float*)d_in[6];
    const float* eeb2  = (const float*)d_in[7];
    const float* W[4]  = {(const float*)d_in[8],  (const float*)d_in[10],
                          (const float*)d_in[12], (const float*)d_in[14]};
    const float* cbp[4]= {(const float*)d_in[9],  (const float*)d_in[11],
                          (const float*)d_in[13], (const float*)d_in[15]};
    const float* gm[4] = {(const float*)d_in[16], (const float*)d_in[18],
                          (const float*)d_in[20], (const float*)d_in[22]};
    const float* be[4] = {(const float*)d_in[17], (const float*)d_in[19],
                          (const float*)d_in[21], (const float*)d_in[23]};
    const float* resW  = (const float*)d_in[24];
    const float* resB  = (const float*)d_in[25];
    const float* hW1   = (const float*)d_in[26];
    const float* hb1   = (const float*)d_in[27];
    const float* hW2   = (const float*)d_in[28];
    const float* hb2   = (const float*)d_in[29];
    float* out = (float*)d_out;

    cudaFuncSetAttribute(mma_gemm_k, cudaFuncAttributeMaxDynamicSharedMemorySize, SMEM_GEMM);

    const int nblkN = (NN + 255) / 256;
    const int nblkE = (EE + 255) / 256;
    const int tileG = (NN + 127) / 128;
    const int aggG  = (NN + 15) / 16;   // 2 nodes per warp, 8 warps per block
    const int edgeG = EE / (128 * ETILES);

    init_k<<<nblkN, 256>>>();
    prep_e_k<<<1, 128>>>(eeW1);
    prep_k<<<5, 128>>>(resW, W[0], W[1], W[2], W[3]);
    edge_mma_k<<<edgeG, 256>>>(ea, eeb1, eeW2, eeb2, ei + EE);
    dis_k<<<nblkN, 256>>>();
    scan1_k<<<SCAN_BLOCKS, 1024>>>();
    scan2_k<<<1, 128>>>();
    scan3_k<<<SCAN_BLOCKS, 1024>>>();
    fill_k<<<nblkE, 256>>>(ei, ei + EE);

    // layer 0: fused GEMM (x@W0 -> hwh ; x@resW+resB -> res0)
    mma_gemm_k<<<tileG, 256, SMEM_GEMM>>>(x, -1, 0, 1, IN_C, nullptr, 1, 0, resB);
    agg_ln_k<<<aggG, 256>>>(cbp[0], gm[0], be[0], -1, 0);
    // layer 1
    mma_gemm_k<<<tileG, 256, SMEM_GEMM>>>(nullptr, 0, 0, 2, HID, nullptr, 0, -1, nullptr);
    agg_ln_k<<<aggG, 256>>>(cbp[1], gm[1], be[1], 0, 1);
    // layer 2
    mma_gemm_k<<<tileG, 256, SMEM_GEMM>>>(nullptr, 1, 0, 3, HID, nullptr, 0, -1, nullptr);
    agg_ln_k<<<aggG, 256>>>(cbp[2], gm[2], be[2], 1, 2);
    // layer 3
    mma_gemm_k<<<tileG, 256, SMEM_GEMM>>>(nullptr, 2, 0, 4, HID, nullptr, 0, -1, nullptr);
    agg_ln_k<<<aggG, 256>>>(cbp[3], gm[3], be[3], 2, 3);

    mark_k<<<nblkN, 256>>>(batch);
    fix_k<<<1, 512>>>();
    pool_k<<<GG, 128>>>();
    head_k<<<GG, 128>>>(hW1, hb1, hW2, hb2, out);
}

// round 13
// speedup vs baseline: 1.0082x; 1.0082x over previous
#include <cuda_runtime.h>
#include <cuda_bf16.h>
#include <cuda_fp16.h>
#include <math.h>
#include <stdint.h>

#define NN   100000
#define EE   1600000
#define GG   512
#define IN_C 96
#define HID  128
#define NCLS 100
#define SCAN_BLOCKS 98   // ceil(100000/1024)
#define ETILES 4         // edge tiles per block (512 edges)

// ---------------- scratch (device globals; no allocation) ----------------
__device__ float  d_ew[EE];
__device__ int    d_pos[EE];
__device__ int    d_cnt[NN];
__device__ int    d_rowptr[NN + 1];
__device__ int    d_bsum[SCAN_BLOCKS];
__device__ int    d_boff[SCAN_BLOCKS];
__device__ float2 d_adj[EE];            // packed (src as int bits, norm)
__device__ float  d_deg[NN];
__device__ float  d_dis[NN];
__device__ __half d_hwh[(size_t)NN * HID];        // GEMM output (gather source)
__device__ __half d_hall[4 * (size_t)NN * HID];   // per-layer hidden activations
__device__ float  d_res0[(size_t)NN * HID];
__device__ int    d_gstart[GG + 1];
__device__ float  d_gmean[GG * HID];
__device__ float  d_gmaxv[GG * HID];
// pre-split weights, n-major [128 n][128 k] bf16, hi and lo parts, 5 matrices
__device__ __nv_bfloat16 d_Bh[5 * 128 * 128];
__device__ __nv_bfloat16 d_Bl[5 * 128 * 128];
// edge-MLP W1 pre-packed, n-major [128 n][16 k]
__device__ __nv_bfloat16 d_EB1[128 * 16];
__device__ __nv_bfloat16 d_EB2[128 * 16];

// ---------------- init ----------------
__global__ void init_k() {
    int i = blockIdx.x * blockDim.x + threadIdx.x;
    if (i < NN) { d_deg[i] = 1.0f; d_cnt[i] = 0; }
    if (i <= GG) d_gstart[i] = NN;
}

// ---------------- mma helper ----------------
__device__ __forceinline__ void mma16816(float* c, const uint32_t* a, const uint32_t* b) {
    asm volatile(
        "mma.sync.aligned.m16n8k16.row.col.f32.bf16.bf16.f32 "
        "{%0,%1,%2,%3}, {%4,%5,%6,%7}, {%8,%9}, {%0,%1,%2,%3};"
        : "+f"(c[0]), "+f"(c[1]), "+f"(c[2]), "+f"(c[3])
        : "r"(a[0]), "r"(a[1]), "r"(a[2]), "r"(a[3]), "r"(b[0]), "r"(b[1]));
}

__device__ __forceinline__ void split_bf16(float v, __nv_bfloat16& h, __nv_bfloat16& l) {
    h = __float2bfloat16_rn(v);
    l = __float2bfloat16_rn(v - __bfloat162float(h));
}

__device__ __forceinline__ uint32_t pack_bf16(__nv_bfloat16 a, __nv_bfloat16 b) {
    return ((uint32_t)__bfloat16_as_ushort(b) << 16) | __bfloat16_as_ushort(a);
}

// ---------------- edge W1 prep ----------------
__global__ __launch_bounds__(128) void prep_e_k(const float* __restrict__ W1) {
    int n = threadIdx.x;
    __nv_bfloat16 z = __float2bfloat16_rn(0.f);
    for (int k = 0; k < 8; k++) {
        float v = W1[k * 128 + n];
        __nv_bfloat16 h, l;
        split_bf16(v, h, l);
        d_EB1[n * 16 + k] = h;
        d_EB1[n * 16 + 8 + k] = h;
        d_EB2[n * 16 + k] = l;
        d_EB2[n * 16 + 8 + k] = z;
    }
}

// ---------------- tensor-core edge MLP + softplus + deg/count ----------------
// A fragments loaded DIRECTLY from gmem (no smem A staging).
// A tile logical layout: k0..7 = hi(attr), k8..15 = lo(attr).
#define EPITCH 24
__global__ __launch_bounds__(256) void edge_mma_k(
    const float* __restrict__ ea, const float* __restrict__ b1,
    const float* __restrict__ W2, const float* __restrict__ b2v,
    const int* __restrict__ col)
{
    __shared__ __nv_bfloat16 B1s[128 * EPITCH];
    __shared__ __nv_bfloat16 B2s[128 * EPITCH];
    __shared__ float b1s[128];
    __shared__ float W2s[128];
    __shared__ float part[128][2];

    int tid = threadIdx.x;
    int eb = blockIdx.x * (128 * ETILES);

    if (tid < 128) { b1s[tid] = b1[tid]; W2s[tid] = W2[tid]; }

    for (int i = tid; i < 128 * 16; i += 256) {
        int n = i >> 4, k = i & 15;
        B1s[n * EPITCH + k] = d_EB1[i];
        B2s[n * EPITCH + k] = d_EB2[i];
    }
    __syncthreads();

    int wid = tid >> 5, lane = tid & 31;
    int g = lane >> 2, tig = lane & 3;
    int wr = (wid & 3) * 32;
    int wc = (wid >> 2) * 64;

    // hoist B fragments into registers (constant across tiles)
    uint32_t b1f[8][2], b2f[8][2];
    #pragma unroll
    for (int nt = 0; nt < 8; nt++) {
        const __nv_bfloat16* nb1 = B1s + (wc + nt * 8 + g) * EPITCH;
        const __nv_bfloat16* nb2 = B2s + (wc + nt * 8 + g) * EPITCH;
        b1f[nt][0] = *(const uint32_t*)(nb1 + 2 * tig);
        b1f[nt][1] = *(const uint32_t*)(nb1 + 8 + 2 * tig);
        b2f[nt][0] = *(const uint32_t*)(nb2 + 2 * tig);
        b2f[nt][1] = *(const uint32_t*)(nb2 + 8 + 2 * tig);
    }
    __syncthreads();   // B1s/B2s fully read into regs before part[] aliasing concerns

    for (int t = 0; t < ETILES; t++) {
        int e0 = eb + t * 128;

        // A fragments directly from gmem:
        // af[mt][0]: row wr+mt*16+g,   cols 2tig..2tig+1 (hi)
        // af[mt][1]: row wr+mt*16+g+8, cols 2tig..2tig+1 (hi)
        // af[mt][2]: same row as [0], k+8 -> lo ; af[mt][3]: row+8 lo
        uint32_t af[2][4];
        #pragma unroll
        for (int mt = 0; mt < 2; mt++) {
            int r0e = e0 + wr + mt * 16 + g;
            float2 v0 = *(const float2*)(ea + (size_t)r0e * 8 + 2 * tig);
            float2 v1 = *(const float2*)(ea + (size_t)(r0e + 8) * 8 + 2 * tig);
            __nv_bfloat16 h0, l0, h1, l1, h2, l2, h3, l3;
            split_bf16(v0.x, h0, l0); split_bf16(v0.y, h1, l1);
            split_bf16(v1.x, h2, l2); split_bf16(v1.y, h3, l3);
            af[mt][0] = pack_bf16(h0, h1);
            af[mt][1] = pack_bf16(h2, h3);
            af[mt][2] = pack_bf16(l0, l1);
            af[mt][3] = pack_bf16(l2, l3);
        }

        // per-nt MMA + immediate relu·W2 consumption
        float s0[2] = {0.f, 0.f}, s8[2] = {0.f, 0.f};
        #pragma unroll
        for (int nt = 0; nt < 8; nt++) {
            float c0[4] = {0.f, 0.f, 0.f, 0.f};
            float c1[4] = {0.f, 0.f, 0.f, 0.f};
            mma16816(c0, af[0], b1f[nt]);
            mma16816(c1, af[1], b1f[nt]);
            mma16816(c0, af[0], b2f[nt]);
            mma16816(c1, af[1], b2f[nt]);
            int c = wc + nt * 8 + 2 * tig;
            float w0 = W2s[c], w1 = W2s[c + 1];
            float bb0 = b1s[c], bb1 = b1s[c + 1];
            s0[0] = fmaf(fmaxf(c0[0] + bb0, 0.f), w0, s0[0]);
            s0[0] = fmaf(fmaxf(c0[1] + bb1, 0.f), w1, s0[0]);
            s8[0] = fmaf(fmaxf(c0[2] + bb0, 0.f), w0, s8[0]);
            s8[0] = fmaf(fmaxf(c0[3] + bb1, 0.f), w1, s8[0]);
            s0[1] = fmaf(fmaxf(c1[0] + bb0, 0.f), w0, s0[1]);
            s0[1] = fmaf(fmaxf(c1[1] + bb1, 0.f), w1, s0[1]);
            s8[1] = fmaf(fmaxf(c1[2] + bb0, 0.f), w0, s8[1]);
            s8[1] = fmaf(fmaxf(c1[3] + bb1, 0.f), w1, s8[1]);
        }
        #pragma unroll
        for (int mt = 0; mt < 2; mt++) {
            float v0 = s0[mt], v8 = s8[mt];
            v0 += __shfl_xor_sync(0xffffffffu, v0, 1);
            v0 += __shfl_xor_sync(0xffffffffu, v0, 2);
            v8 += __shfl_xor_sync(0xffffffffu, v8, 1);
            v8 += __shfl_xor_sync(0xffffffffu, v8, 2);
            if (tig == 0) {
                int wn = wid >> 2;
                part[wr + mt * 16 + g][wn] = v0;
                part[wr + mt * 16 + g + 8][wn] = v8;
            }
        }
        __syncthreads();

        if (tid < 128) {
            int e = e0 + tid;
            float x = part[tid][0] + part[tid][1] + b2v[0];
            float sp = (x > 15.f) ? x : log1pf(expf(x));
            float ew = sp + 1e-4f;
            d_ew[e] = ew;
            int c = col[e];
            d_pos[e] = atomicAdd(&d_cnt[c], 1);
            atomicAdd(&d_deg[c], ew);
        }
        __syncthreads();
    }
}

__global__ void dis_k() {
    int i = blockIdx.x * blockDim.x + threadIdx.x;
    if (i < NN) d_dis[i] = rsqrtf(d_deg[i]);
}

// ---------------- hierarchical scan ----------------
__global__ __launch_bounds__(1024) void scan1_k() {
    __shared__ int wsum[32];
    int tid = threadIdx.x, lane = tid & 31, wid = tid >> 5;
    int i = blockIdx.x * 1024 + tid;
    int v = (i < NN) ? d_cnt[i] : 0;
    int s = v;
    #pragma unroll
    for (int o = 1; o < 32; o <<= 1) {
        int t = __shfl_up_sync(0xffffffffu, s, o);
        if (lane >= o) s += t;
    }
    if (lane == 31) wsum[wid] = s;
    __syncthreads();
    if (wid == 0) {
        int ws = wsum[lane];
        #pragma unroll
        for (int o = 1; o < 32; o <<= 1) {
            int t = __shfl_up_sync(0xffffffffu, ws, o);
            if (lane >= o) ws += t;
        }
        wsum[lane] = ws;
    }
    __syncthreads();
    int incl = s + ((wid > 0) ? wsum[wid - 1] : 0);
    if (i < NN) d_rowptr[i + 1] = incl;
    if (tid == 1023) d_bsum[blockIdx.x] = incl;
}

__global__ __launch_bounds__(128) void scan2_k() {
    int tid = threadIdx.x, lane = tid & 31, wid = tid >> 5;
    __shared__ int wsum[4];
    int v = (tid < SCAN_BLOCKS) ? d_bsum[tid] : 0;
    int s = v;
    #pragma unroll
    for (int o = 1; o < 32; o <<= 1) {
        int t = __shfl_up_sync(0xffffffffu, s, o);
        if (lane >= o) s += t;
    }
    if (lane == 31) wsum[wid] = s;
    __syncthreads();
    int add = 0;
    for (int w = 0; w < 4; w++) if (w < wid) add += wsum[w];
    if (tid < SCAN_BLOCKS) d_boff[tid] = s + add - v;
}

__global__ __launch_bounds__(1024) void scan3_k() {
    int i = blockIdx.x * 1024 + threadIdx.x;
    if (i < NN) d_rowptr[i + 1] += d_boff[blockIdx.x];
    if (i == 0) d_rowptr[0] = 0;
}

// ---------------- fill CSR (packed src+norm) ----------------
__global__ void fill_k(const int* __restrict__ row, const int* __restrict__ col) {
    int e = blockIdx.x * blockDim.x + threadIdx.x;
    if (e >= EE) return;
    int r = row[e], c = col[e];
    int j = d_rowptr[c] + d_pos[e];
    float2 v;
    v.x = __int_as_float(r);
    v.y = d_dis[r] * d_ew[e] * d_dis[c];
    d_adj[j] = v;
}

// ---------------- weight prep ----------------
__global__ __launch_bounds__(128) void prep_k(
    const float* __restrict__ resW, const float* __restrict__ W0,
    const float* __restrict__ W1, const float* __restrict__ W2,
    const float* __restrict__ W3)
{
    int m = blockIdx.x, n = threadIdx.x;
    const float* W; int K;
    switch (m) {
        case 0: W = resW; K = 96; break;
        case 1: W = W0;   K = 96; break;
        case 2: W = W1;   K = 128; break;
        case 3: W = W2;   K = 128; break;
        default: W = W3;  K = 128; break;
    }
    __nv_bfloat16* bh = d_Bh + (size_t)m * 16384 + (size_t)n * 128;
    __nv_bfloat16* bl = d_Bl + (size_t)m * 16384 + (size_t)n * 128;
    for (int k = 0; k < 128; k++) {
        float v = (k < K) ? W[(size_t)k * HID + n] : 0.f;
        __nv_bfloat16 h, l;
        split_bf16(v, h, l);
        bh[k] = h;
        bl[k] = l;
    }
}

// ---------------- HMMA bf16 split GEMM ----------------
#define PITCH 136
#define BUFSZ (128 * PITCH)
#define SMEM_GEMM (4 * BUFSZ * 2)

// asel: -1 -> Ain fp32 (lda cols) ; 0..3 -> d_hall[asel] fp16 (128 cols)
__global__ __launch_bounds__(256) void mma_gemm_k(
    const float* __restrict__ Ain, int asel, int osel, int mat,
    int lda, const float* __restrict__ bias,
    int osel2, int mat2, const float* __restrict__ bias2)
{
    extern __shared__ __nv_bfloat16 sm[];
    __nv_bfloat16* AhiS = sm;
    __nv_bfloat16* AloS = sm + BUFSZ;
    __nv_bfloat16* BhS  = sm + 2 * BUFSZ;
    __nv_bfloat16* BlS  = sm + 3 * BUFSZ;
    __shared__ float biasS[128];

    int tid = threadIdx.x;
    int r0 = blockIdx.x * 128;

    // stage A (fp32 or fp16 -> hi/lo bf16) once
    {
        const __half* A16 = (asel >= 0) ? (d_hall + (size_t)asel * NN * HID) : nullptr;
        int rr = tid >> 5;
        int cc = (tid & 31) * 4;
        #pragma unroll 4
        for (int it = 0; it < 16; it++) {
            int r = it * 8 + rr;
            int R = r0 + r;
            float4 v = make_float4(0.f, 0.f, 0.f, 0.f);
            if (asel >= 0) {
                if (R < NN) {
                    uint2 raw = *(const uint2*)(A16 + (size_t)R * HID + cc);
                    float2 f0 = __half22float2(*(__half2*)&raw.x);
                    float2 f1 = __half22float2(*(__half2*)&raw.y);
                    v = make_float4(f0.x, f0.y, f1.x, f1.y);
                }
            } else {
                if (R < NN && cc < lda)
                    v = *(const float4*)(Ain + (size_t)R * lda + cc);
            }
            __nv_bfloat16 h0, l0, h1, l1, h2, l2, h3, l3;
            split_bf16(v.x, h0, l0); split_bf16(v.y, h1, l1);
            split_bf16(v.z, h2, l2); split_bf16(v.w, h3, l3);
            uint2 ph, pl;
            ph.x = pack_bf16(h0, h1);
            ph.y = pack_bf16(h2, h3);
            pl.x = pack_bf16(l0, l1);
            pl.y = pack_bf16(l2, l3);
            *(uint2*)(AhiS + r * PITCH + cc) = ph;
            *(uint2*)(AloS + r * PITCH + cc) = pl;
        }
    }

    int wid = tid >> 5, lane = tid & 31;
    int g = lane >> 2, tig = lane & 3;
    int wr = (wid & 3) * 32;
    int wc = (wid >> 2) * 64;

    int curMat = mat, curOsel = osel;
    const float* curBias = bias;

    for (int pass = 0; pass < 2; pass++) {
        if (pass == 1) {
            if (mat2 < 0) break;
            curMat = mat2; curOsel = osel2; curBias = bias2;
            __syncthreads();
        }
        {
            int rr = tid >> 5;
            int cc = (tid & 31) * 4;
            const __nv_bfloat16* gh = d_Bh + (size_t)curMat * 16384;
            const __nv_bfloat16* gl = d_Bl + (size_t)curMat * 16384;
            #pragma unroll 4
            for (int it = 0; it < 16; it++) {
                int n = it * 8 + rr;
                *(uint2*)(BhS + n * PITCH + cc) = *(const uint2*)(gh + n * 128 + cc);
                *(uint2*)(BlS + n * PITCH + cc) = *(const uint2*)(gl + n * 128 + cc);
            }
        }
        if (tid < 128) biasS[tid] = curBias ? curBias[tid] : 0.f;
        __syncthreads();

        float cacc[2][8][4];
        #pragma unroll
        for (int mt = 0; mt < 2; mt++)
            #pragma unroll
            for (int nt = 0; nt < 8; nt++)
                #pragma unroll
                for (int q = 0; q < 4; q++) cacc[mt][nt][q] = 0.f;

        #pragma unroll
        for (int p = 0; p < 3; p++) {
            const __nv_bfloat16* As = (p == 1) ? AloS : AhiS;
            const __nv_bfloat16* Bs = (p == 2) ? BlS : BhS;
            #pragma unroll
            for (int ks = 0; ks < 8; ks++) {
                int k0 = ks * 16;
                uint32_t af[2][4];
                #pragma unroll
                for (int mt = 0; mt < 2; mt++) {
                    const __nv_bfloat16* base = As + (wr + mt * 16) * PITCH + k0;
                    af[mt][0] = *(const uint32_t*)(base + g * PITCH + 2 * tig);
                    af[mt][1] = *(const uint32_t*)(base + (g + 8) * PITCH + 2 * tig);
                    af[mt][2] = *(const uint32_t*)(base + g * PITCH + 8 + 2 * tig);
                    af[mt][3] = *(const uint32_t*)(base + (g + 8) * PITCH + 8 + 2 * tig);
                }
                #pragma unroll
                for (int nt = 0; nt < 8; nt++) {
                    uint32_t bf[2];
                    const __nv_bfloat16* nb = Bs + (wc + nt * 8 + g) * PITCH + k0;
                    bf[0] = *(const uint32_t*)(nb + 2 * tig);
                    bf[1] = *(const uint32_t*)(nb + 8 + 2 * tig);
                    mma16816(cacc[0][nt], af[0], bf);
                    mma16816(cacc[1][nt], af[1], bf);
                }
            }
        }

        #pragma unroll
        for (int mt = 0; mt < 2; mt++) {
            int row = r0 + wr + mt * 16 + g;
            #pragma unroll
            for (int nt = 0; nt < 8; nt++) {
                int col = wc + nt * 8 + 2 * tig;
                float b0 = biasS[col], b1 = biasS[col + 1];
                float v00 = cacc[mt][nt][0] + b0, v01 = cacc[mt][nt][1] + b1;
                float v10 = cacc[mt][nt][2] + b0, v11 = cacc[mt][nt][3] + b1;
                if (curOsel == 1) {
                    if (row < NN)
                        *(float2*)(d_res0 + (size_t)row * HID + col) = make_float2(v00, v01);
                    if (row + 8 < NN)
                        *(float2*)(d_res0 + (size_t)(row + 8) * HID + col) = make_float2(v10, v11);
                } else {
                    if (row < NN)
                        *(__half2*)(d_hwh + (size_t)row * HID + col) =
                            __floats2half2_rn(v00, v01);
                    if (row + 8 < NN)
                        *(__half2*)(d_hwh + (size_t)(row + 8) * HID + col) =
                            __floats2half2_rn(v10, v11);
                }
            }
        }
    }
}

// ---------------- fused aggregate + bias + LN + residual + relu -> fp16 h ----------------
__device__ __forceinline__ void acc_edge(float4& acc, float w, uint2 raw) {
    float2 f0 = __half22float2(*(__half2*)&raw.x);
    float2 f1 = __half22float2(*(__half2*)&raw.y);
    acc.x = fmaf(w, f0.x, acc.x);
    acc.y = fmaf(w, f0.y, acc.y);
    acc.z = fmaf(w, f1.x, acc.z);
    acc.w = fmaf(w, f1.y, acc.w);
}

// rsel: -1 -> d_res0 (fp32), 0..3 -> d_hall[rsel] fp16 ; hsel: output layer index
__global__ __launch_bounds__(256) void agg_ln_k(
    const float* __restrict__ cb, const float* __restrict__ gam,
    const float* __restrict__ bet, int rsel, int hsel)
{
    int n = (blockIdx.x * 256 + threadIdx.x) >> 5;
    if (n >= NN) return;
    int lane = threadIdx.x & 31;
    const uint2* hw2 = (const uint2*)d_hwh;
    size_t loff = (size_t)lane;

    float dn = d_dis[n];
    float sn = dn * dn;
    float4 acc = ((const float4*)cb)[lane];
    acc_edge(acc, sn, hw2[(size_t)n * 32 + loff]);

    int jb = d_rowptr[n], je = d_rowptr[n + 1];
    int j = jb;
    for (; j + 4 <= je; j += 4) {
        float2 a0 = d_adj[j];
        float2 a1 = d_adj[j + 1];
        float2 a2 = d_adj[j + 2];
        float2 a3 = d_adj[j + 3];
        uint2 r0 = hw2[(size_t)__float_as_int(a0.x) * 32 + loff];
        uint2 r1 = hw2[(size_t)__float_as_int(a1.x) * 32 + loff];
        uint2 r2 = hw2[(size_t)__float_as_int(a2.x) * 32 + loff];
        uint2 r3 = hw2[(size_t)__float_as_int(a3.x) * 32 + loff];
        acc_edge(acc, a0.y, r0);
        acc_edge(acc, a1.y, r1);
        acc_edge(acc, a2.y, r2);
        acc_edge(acc, a3.y, r3);
    }
    for (; j < je; j++) {
        float2 a = d_adj[j];
        acc_edge(acc, a.y, hw2[(size_t)__float_as_int(a.x) * 32 + loff]);
    }

    float ss = acc.x + acc.y + acc.z + acc.w;
    #pragma unroll
    for (int o = 16; o > 0; o >>= 1) ss += __shfl_xor_sync(0xffffffffu, ss, o);
    float mu = ss * (1.f / 128.f);
    float dx0 = acc.x - mu, dx1 = acc.y - mu, dx2 = acc.z - mu, dx3 = acc.w - mu;
    float q = dx0 * dx0 + dx1 * dx1 + dx2 * dx2 + dx3 * dx3;
    #pragma unroll
    for (int o = 16; o > 0; o >>= 1) q += __shfl_xor_sync(0xffffffffu, q, o);
    float rstd = rsqrtf(q * (1.f / 128.f) + 1e-5f);

    float4 gv = ((const float4*)gam)[lane];
    float4 bv = ((const float4*)bet)[lane];
    float4 rv;
    if (rsel < 0) {
        rv = ((const float4*)d_res0)[(size_t)n * 32 + lane];
    } else {
        const __half* rp = d_hall + (size_t)rsel * NN * HID;
        uint2 raw = *(const uint2*)(rp + (size_t)n * HID + lane * 4);
        float2 f0 = __half22float2(*(__half2*)&raw.x);
        float2 f1 = __half22float2(*(__half2*)&raw.y);
        rv = make_float4(f0.x, f0.y, f1.x, f1.y);
    }
    float4 h;
    h.x = fmaxf(fmaf(gv.x, dx0 * rstd, bv.x) + rv.x, 0.f);
    h.y = fmaxf(fmaf(gv.y, dx1 * rstd, bv.y) + rv.y, 0.f);
    h.z = fmaxf(fmaf(gv.z, dx2 * rstd, bv.z) + rv.z, 0.f);
    h.w = fmaxf(fmaf(gv.w, dx3 * rstd, bv.w) + rv.w, 0.f);

    __half* hb = d_hall + (size_t)hsel * NN * HID;
    uint2 pk;
    *(__half2*)&pk.x = __floats2half2_rn(h.x, h.y);
    *(__half2*)&pk.y = __floats2half2_rn(h.z, h.w);
    *(uint2*)(hb + (size_t)n * HID + lane * 4) = pk;
}

// ---------------- graph segment boundaries ----------------
__global__ void mark_k(const int* __restrict__ batch) {
    int n = blockIdx.x * blockDim.x + threadIdx.x;
    if (n >= NN) return;
    int b = batch[n];
    if (n == 0 || batch[n - 1] != b) atomicMin(&d_gstart[b], n);
}

__global__ __launch_bounds__(512) void fix_k() {
    __shared__ int s[520];
    int t = threadIdx.x;
    s[t] = d_gstart[t];
    if (t == 0) s[GG] = NN;
    __syncthreads();
    for (int o = 1; o <= GG; o <<= 1) {
        int v = s[t];
        int u = (t + o <= GG) ? s[t + o] : NN;
        __syncthreads();
        s[t] = min(v, u);
        __syncthreads();
    }
    d_gstart[t] = s[t];
}

// ---------------- pooling: mean+max of (h0+h1+h2+h3)/4 over each graph ----------------
__global__ __launch_bounds__(128) void pool_k() {
    int g = blockIdx.x, c = threadIdx.x;
    int s = d_gstart[g], e = d_gstart[g + 1];
    const __half* h0 = d_hall;
    const __half* h1 = d_hall + (size_t)NN * HID;
    const __half* h2 = d_hall + 2 * (size_t)NN * HID;
    const __half* h3 = d_hall + 3 * (size_t)NN * HID;
    float sum = 0.f, mx = 0.f;
    for (int n = s; n < e; n++) {
        size_t off = (size_t)n * HID + c;
        float v = (__half2float(h0[off]) + __half2float(h1[off])
                 + __half2float(h2[off]) + __half2float(h3[off])) * 0.25f;
        sum += v;
        mx = fmaxf(mx, v);
    }
    int cnt = e - s;
    d_gmean[g * HID + c] = sum / (float)max(cnt, 1);
    d_gmaxv[g * HID + c] = mx;
}

// ---------------- head ----------------
__global__ __launch_bounds__(128) void head_k(
    const float* __restrict__ hW1, const float* __restrict__ hb1,
    const float* __restrict__ hW2, const float* __restrict__ hb2,
    float* __restrict__ out)
{
    __shared__ float gf[256];
    __shared__ float h1s[128];
    int g = blockIdx.x, t = threadIdx.x;
    gf[t] = d_gmean[g * HID + t];
    gf[128 + t] = d_gmaxv[g * HID + t];
    __syncthreads();
    float acc = hb1[t];
    #pragma unroll 8
    for (int k = 0; k < 256; k++) acc = fmaf(gf[k], hW1[k * HID + t], acc);
    h1s[t] = fmaxf(acc, 0.f);
    __syncthreads();
    if (t < NCLS) {
        float o = hb2[t];
        #pragma unroll 8
        for (int k = 0; k < 128; k++) o = fmaf(h1s[k], hW2[k * NCLS + t], o);
        out[g * NCLS + t] = o;
    }
}

// ---------------- launcher ----------------
extern "C" void kernel_launch(void* const* d_in, const int* in_sizes, int n_in,
                              void* d_out, int out_size) {
    const float* x     = (const float*)d_in[0];
    const int*   ei    = (const int*)d_in[1];
    const int*   batch = (const int*)d_in[2];
    const float* ea    = (const float*)d_in[3];
    const float* eeW1  = (const float*)d_in[4];
    const float* eeb1  = (const float*)d_in[5];
    const float* eeW2  = (const float*)d_in[6];
    const float* eeb2  = (const float*)d_in[7];
    const float* W[4]  = {(const float*)d_in[8],  (const float*)d_in[10],
                          (const float*)d_in[12], (const float*)d_in[14]};
    const float* cbp[4]= {(const float*)d_in[9],  (const float*)d_in[11],
                          (const float*)d_in[13], (const float*)d_in[15]};
    const float* gm[4] = {(const float*)d_in[16], (const float*)d_in[18],
                          (const float*)d_in[20], (const float*)d_in[22]};
    const float* be[4] = {(const float*)d_in[17], (const float*)d_in[19],
                          (const float*)d_in[21], (const float*)d_in[23]};
    const float* resW  = (const float*)d_in[24];
    const float* resB  = (const float*)d_in[25];
    const float* hW1   = (const float*)d_in[26];
    const float* hb1   = (const float*)d_in[27];
    const float* hW2   = (const float*)d_in[28];
    const float* hb2   = (const float*)d_in[29];
    float* out = (float*)d_out;

    cudaFuncSetAttribute(mma_gemm_k, cudaFuncAttributeMaxDynamicSharedMemorySize, SMEM_GEMM);

    const int nblkN = (NN + 255) / 256;
    const int nblkE = (EE + 255) / 256;
    const int tileG = (NN + 127) / 128;
    const int aggG  = (NN + 7) / 8;
    const int edgeG = EE / (128 * ETILES);

    init_k<<<nblkN, 256>>>();
    prep_e_k<<<1, 128>>>(eeW1);
    prep_k<<<5, 128>>>(resW, W[0], W[1], W[2], W[3]);
    edge_mma_k<<<edgeG, 256>>>(ea, eeb1, eeW2, eeb2, ei + EE);
    dis_k<<<nblkN, 256>>>();
    scan1_k<<<SCAN_BLOCKS, 1024>>>();
    scan2_k<<<1, 128>>>();
    scan3_k<<<SCAN_BLOCKS, 1024>>>();
    fill_k<<<nblkE, 256>>>(ei, ei + EE);

    // layer 0: fused GEMM (x@W0 -> hwh ; x@resW+resB -> res0)
    mma_gemm_k<<<tileG, 256, SMEM_GEMM>>>(x, -1, 0, 1, IN_C, nullptr, 1, 0, resB);
    agg_ln_k<<<aggG, 256>>>(cbp[0], gm[0], be[0], -1, 0);
    // layer 1
    mma_gemm_k<<<tileG, 256, SMEM_GEMM>>>(nullptr, 0, 0, 2, HID, nullptr, 0, -1, nullptr);
    agg_ln_k<<<aggG, 256>>>(cbp[1], gm[1], be[1], 0, 1);
    // layer 2
    mma_gemm_k<<<tileG, 256, SMEM_GEMM>>>(nullptr, 1, 0, 3, HID, nullptr, 0, -1, nullptr);
    agg_ln_k<<<aggG, 256>>>(cbp[2], gm[2], be[2], 1, 2);
    // layer 3
    mma_gemm_k<<<tileG, 256, SMEM_GEMM>>>(nullptr, 2, 0, 4, HID, nullptr, 0, -1, nullptr);
    agg_ln_k<<<aggG, 256>>>(cbp[3], gm[3], be[3], 2, 3);

    mark_k<<<nblkN, 256>>>(batch);
    fix_k<<<1, 512>>>();
    pool_k<<<GG, 128>>>();
    head_k<<<GG, 128>>>(hW1, hb1, hW2, hb2, out);
}

// round 15
// speedup vs baseline: 1.0451x; 1.0366x over previous
#include <cuda_runtime.h>
#include <cuda_bf16.h>
#include <cuda_fp16.h>
#include <math.h>
#include <stdint.h>

#define NN   100000
#define EE   1600000
#define GG   512
#define IN_C 96
#define HID  128
#define NCLS 100
#define SCAN_BLOCKS 98   // ceil(100000/1024)
#define ETILES 4         // edge tiles per block (512 edges) — measured best

// ---------------- scratch (device globals; no allocation) ----------------
__device__ float  d_ew[EE];
__device__ int    d_pos[EE];
__device__ int    d_cnt[NN];
__device__ int    d_rowptr[NN + 1];
__device__ int    d_bsum[SCAN_BLOCKS];
__device__ int    d_boff[SCAN_BLOCKS];
__device__ float2 d_adj[EE];            // packed (src as int bits, norm)
__device__ float  d_deg[NN];
__device__ float  d_dis[NN];
__device__ __half d_hwh[(size_t)NN * HID];        // GEMM output (gather source)
__device__ __half d_hall[4 * (size_t)NN * HID];   // per-layer hidden activations
__device__ float  d_res0[(size_t)NN * HID];
__device__ int    d_gstart[GG + 1];
__device__ float  d_gmean[GG * HID];
__device__ float  d_gmaxv[GG * HID];
// pre-split weights, n-major [128 n][128 k] bf16, hi and lo parts, 5 matrices
__device__ __nv_bfloat16 d_Bh[5 * 128 * 128];
__device__ __nv_bfloat16 d_Bl[5 * 128 * 128];
// edge-MLP W1 packed, n-major [128 n][16 k]: k0..7 = hi(W1), k8..15 = lo(W1)
__device__ __nv_bfloat16 d_EB1[128 * 16];

// ---------------- init ----------------
__global__ void init_k() {
    int i = blockIdx.x * blockDim.x + threadIdx.x;
    if (i < NN) { d_deg[i] = 1.0f; d_cnt[i] = 0; }
    if (i <= GG) d_gstart[i] = NN;
}

// ---------------- mma helper ----------------
__device__ __forceinline__ void mma16816(float* c, const uint32_t* a, const uint32_t* b) {
    asm volatile(
        "mma.sync.aligned.m16n8k16.row.col.f32.bf16.bf16.f32 "
        "{%0,%1,%2,%3}, {%4,%5,%6,%7}, {%8,%9}, {%0,%1,%2,%3};"
        : "+f"(c[0]), "+f"(c[1]), "+f"(c[2]), "+f"(c[3])
        : "r"(a[0]), "r"(a[1]), "r"(a[2]), "r"(a[3]), "r"(b[0]), "r"(b[1]));
}

__device__ __forceinline__ void split_bf16(float v, __nv_bfloat16& h, __nv_bfloat16& l) {
    h = __float2bfloat16_rn(v);
    l = __float2bfloat16_rn(v - __bfloat162float(h));
}

__device__ __forceinline__ uint32_t pack_bf16(__nv_bfloat16 a, __nv_bfloat16 b) {
    return ((uint32_t)__bfloat16_as_ushort(b) << 16) | __bfloat16_as_ushort(a);
}

// ---------------- edge W1 prep: [Bh | Bl] packing ----------------
__global__ __launch_bounds__(128) void prep_e_k(const float* __restrict__ W1) {
    int n = threadIdx.x;
    for (int k = 0; k < 8; k++) {
        float v = W1[k * 128 + n];
        __nv_bfloat16 h, l;
        split_bf16(v, h, l);
        d_EB1[n * 16 + k] = h;
        d_EB1[n * 16 + 8 + k] = l;
    }
}

// ---------------- tensor-core edge MLP + softplus + deg/count ----------------
// Single MMA pass: A = [Ah | Ah] (fragment duplication), B = [Bh | Bl]
//   => C = Ah·Bh + Ah·Bl  (drops attr-lo term; bf16 attr quantization)
#define EPITCH 24
__global__ __launch_bounds__(256) void edge_mma_k(
    const float* __restrict__ ea, const float* __restrict__ b1,
    const float* __restrict__ W2, const float* __restrict__ b2v,
    const int* __restrict__ col)
{
    __shared__ __nv_bfloat16 As[128 * EPITCH];
    __shared__ __nv_bfloat16 B1s[128 * EPITCH];
    __shared__ float b1s[128];
    __shared__ float W2s[128];
    __shared__ float part[128][2];

    int tid = threadIdx.x;
    int eb = blockIdx.x * (128 * ETILES);

    if (tid < 128) { b1s[tid] = b1[tid]; W2s[tid] = W2[tid]; }

    // stage B once per block
    for (int i = tid; i < 128 * 16; i += 256) {
        int n = i >> 4, k = i & 15;
        B1s[n * EPITCH + k] = d_EB1[i];
    }
    __syncthreads();

    int wid = tid >> 5, lane = tid & 31;
    int g = lane >> 2, tig = lane & 3;
    int wr = (wid & 3) * 32;
    int wc = (wid >> 2) * 64;
    int eS = tid >> 1, half = tid & 1;

    // hoist B fragments into registers (constant across tiles)
    uint32_t b1f[8][2];
    #pragma unroll
    for (int nt = 0; nt < 8; nt++) {
        const __nv_bfloat16* nb1 = B1s + (wc + nt * 8 + g) * EPITCH;
        b1f[nt][0] = *(const uint32_t*)(nb1 + 2 * tig);
        b1f[nt][1] = *(const uint32_t*)(nb1 + 8 + 2 * tig);
    }

    for (int t = 0; t < ETILES; t++) {
        int e0 = eb + t * 128;
        // stage A tile: only hi, k0..7
        {
            float4 v = *(const float4*)(ea + (size_t)(e0 + eS) * 8 + half * 4);
            __nv_bfloat16* ah = As + eS * EPITCH + half * 4;
            ah[0] = __float2bfloat16_rn(v.x);
            ah[1] = __float2bfloat16_rn(v.y);
            ah[2] = __float2bfloat16_rn(v.z);
            ah[3] = __float2bfloat16_rn(v.w);
        }
        __syncthreads();

        // A fragments; duplicate k0..7 into the k8..15 slots
        uint32_t af[2][4];
        #pragma unroll
        for (int mt = 0; mt < 2; mt++) {
            const __nv_bfloat16* base = As + (wr + mt * 16) * EPITCH;
            af[mt][0] = *(const uint32_t*)(base + g * EPITCH + 2 * tig);
            af[mt][1] = *(const uint32_t*)(base + (g + 8) * EPITCH + 2 * tig);
            af[mt][2] = af[mt][0];
            af[mt][3] = af[mt][1];
        }

        // per-nt single-pass MMA + immediate relu·W2 consumption
        float s0[2] = {0.f, 0.f}, s8[2] = {0.f, 0.f};
        #pragma unroll
        for (int nt = 0; nt < 8; nt++) {
            float c0[4] = {0.f, 0.f, 0.f, 0.f};
            float c1[4] = {0.f, 0.f, 0.f, 0.f};
            mma16816(c0, af[0], b1f[nt]);
            mma16816(c1, af[1], b1f[nt]);
            int c = wc + nt * 8 + 2 * tig;
            float w0 = W2s[c], w1 = W2s[c + 1];
            float bb0 = b1s[c], bb1 = b1s[c + 1];
            s0[0] = fmaf(fmaxf(c0[0] + bb0, 0.f), w0, s0[0]);
            s0[0] = fmaf(fmaxf(c0[1] + bb1, 0.f), w1, s0[0]);
            s8[0] = fmaf(fmaxf(c0[2] + bb0, 0.f), w0, s8[0]);
            s8[0] = fmaf(fmaxf(c0[3] + bb1, 0.f), w1, s8[0]);
            s0[1] = fmaf(fmaxf(c1[0] + bb0, 0.f), w0, s0[1]);
            s0[1] = fmaf(fmaxf(c1[1] + bb1, 0.f), w1, s0[1]);
            s8[1] = fmaf(fmaxf(c1[2] + bb0, 0.f), w0, s8[1]);
            s8[1] = fmaf(fmaxf(c1[3] + bb1, 0.f), w1, s8[1]);
        }
        #pragma unroll
        for (int mt = 0; mt < 2; mt++) {
            float v0 = s0[mt], v8 = s8[mt];
            v0 += __shfl_xor_sync(0xffffffffu, v0, 1);
            v0 += __shfl_xor_sync(0xffffffffu, v0, 2);
            v8 += __shfl_xor_sync(0xffffffffu, v8, 1);
            v8 += __shfl_xor_sync(0xffffffffu, v8, 2);
            if (tig == 0) {
                int wn = wid >> 2;
                part[wr + mt * 16 + g][wn] = v0;
                part[wr + mt * 16 + g + 8][wn] = v8;
            }
        }
        __syncthreads();

        if (tid < 128) {
            int e = e0 + tid;
            float x = part[tid][0] + part[tid][1] + b2v[0];
            float sp = (x > 15.f) ? x : log1pf(expf(x));
            float ew = sp + 1e-4f;
            d_ew[e] = ew;
            int c = col[e];
            d_pos[e] = atomicAdd(&d_cnt[c], 1);
            atomicAdd(&d_deg[c], ew);
        }
        __syncthreads();
    }
}

__global__ void dis_k() {
    int i = blockIdx.x * blockDim.x + threadIdx.x;
    if (i < NN) d_dis[i] = rsqrtf(d_deg[i]);
}

// ---------------- hierarchical scan ----------------
__global__ __launch_bounds__(1024) void scan1_k() {
    __shared__ int wsum[32];
    int tid = threadIdx.x, lane = tid & 31, wid = tid >> 5;
    int i = blockIdx.x * 1024 + tid;
    int v = (i < NN) ? d_cnt[i] : 0;
    int s = v;
    #pragma unroll
    for (int o = 1; o < 32; o <<= 1) {
        int t = __shfl_up_sync(0xffffffffu, s, o);
        if (lane >= o) s += t;
    }
    if (lane == 31) wsum[wid] = s;
    __syncthreads();
    if (wid == 0) {
        int ws = wsum[lane];
        #pragma unroll
        for (int o = 1; o < 32; o <<= 1) {
            int t = __shfl_up_sync(0xffffffffu, ws, o);
            if (lane >= o) ws += t;
        }
        wsum[lane] = ws;
    }
    __syncthreads();
    int incl = s + ((wid > 0) ? wsum[wid - 1] : 0);
    if (i < NN) d_rowptr[i + 1] = incl;
    if (tid == 1023) d_bsum[blockIdx.x] = incl;
}

__global__ __launch_bounds__(128) void scan2_k() {
    int tid = threadIdx.x, lane = tid & 31, wid = tid >> 5;
    __shared__ int wsum[4];
    int v = (tid < SCAN_BLOCKS) ? d_bsum[tid] : 0;
    int s = v;
    #pragma unroll
    for (int o = 1; o < 32; o <<= 1) {
        int t = __shfl_up_sync(0xffffffffu, s, o);
        if (lane >= o) s += t;
    }
    if (lane == 31) wsum[wid] = s;
    __syncthreads();
    int add = 0;
    for (int w = 0; w < 4; w++) if (w < wid) add += wsum[w];
    if (tid < SCAN_BLOCKS) d_boff[tid] = s + add - v;
}

__global__ __launch_bounds__(1024) void scan3_k() {
    int i = blockIdx.x * 1024 + threadIdx.x;
    if (i < NN) d_rowptr[i + 1] += d_boff[blockIdx.x];
    if (i == 0) d_rowptr[0] = 0;
}

// ---------------- fill CSR (packed src+norm) ----------------
__global__ void fill_k(const int* __restrict__ row, const int* __restrict__ col) {
    int e = blockIdx.x * blockDim.x + threadIdx.x;
    if (e >= EE) return;
    int r = row[e], c = col[e];
    int j = d_rowptr[c] + d_pos[e];
    float2 v;
    v.x = __int_as_float(r);
    v.y = d_dis[r] * d_ew[e] * d_dis[c];
    d_adj[j] = v;
}

// ---------------- weight prep ----------------
__global__ __launch_bounds__(128) void prep_k(
    const float* __restrict__ resW, const float* __restrict__ W0,
    const float* __restrict__ W1, const float* __restrict__ W2,
    const float* __restrict__ W3)
{
    int m = blockIdx.x, n = threadIdx.x;
    const float* W; int K;
    switch (m) {
        case 0: W = resW; K = 96; break;
        case 1: W = W0;   K = 96; break;
        case 2: W = W1;   K = 128; break;
        case 3: W = W2;   K = 128; break;
        default: W = W3;  K = 128; break;
    }
    __nv_bfloat16* bh = d_Bh + (size_t)m * 16384 + (size_t)n * 128;
    __nv_bfloat16* bl = d_Bl + (size_t)m * 16384 + (size_t)n * 128;
    for (int k = 0; k < 128; k++) {
        float v = (k < K) ? W[(size_t)k * HID + n] : 0.f;
        __nv_bfloat16 h, l;
        split_bf16(v, h, l);
        bh[k] = h;
        bl[k] = l;
    }
}

// ---------------- HMMA bf16 split GEMM ----------------
#define PITCH 136
#define BUFSZ (128 * PITCH)
#define SMEM_GEMM (4 * BUFSZ * 2)

// asel: -1 -> Ain fp32 (lda cols) ; 0..3 -> d_hall[asel] fp16 (128 cols)
__global__ __launch_bounds__(256) void mma_gemm_k(
    const float* __restrict__ Ain, int asel, int osel, int mat,
    int lda, const float* __restrict__ bias,
    int osel2, int mat2, const float* __restrict__ bias2)
{
    extern __shared__ __nv_bfloat16 sm[];
    __nv_bfloat16* AhiS = sm;
    __nv_bfloat16* AloS = sm + BUFSZ;
    __nv_bfloat16* BhS  = sm + 2 * BUFSZ;
    __nv_bfloat16* BlS  = sm + 3 * BUFSZ;
    __shared__ float biasS[128];

    int tid = threadIdx.x;
    int r0 = blockIdx.x * 128;

    // stage A (fp32 or fp16 -> hi/lo bf16) once
    {
        const __half* A16 = (asel >= 0) ? (d_hall + (size_t)asel * NN * HID) : nullptr;
        int rr = tid >> 5;
        int cc = (tid & 31) * 4;
        #pragma unroll 4
        for (int it = 0; it < 16; it++) {
            int r = it * 8 + rr;
            int R = r0 + r;
            float4 v = make_float4(0.f, 0.f, 0.f, 0.f);
            if (asel >= 0) {
                if (R < NN) {
                    uint2 raw = *(const uint2*)(A16 + (size_t)R * HID + cc);
                    float2 f0 = __half22float2(*(__half2*)&raw.x);
                    float2 f1 = __half22float2(*(__half2*)&raw.y);
                    v = make_float4(f0.x, f0.y, f1.x, f1.y);
                }
            } else {
                if (R < NN && cc < lda)
                    v = *(const float4*)(Ain + (size_t)R * lda + cc);
            }
            __nv_bfloat16 h0, l0, h1, l1, h2, l2, h3, l3;
            split_bf16(v.x, h0, l0); split_bf16(v.y, h1, l1);
            split_bf16(v.z, h2, l2); split_bf16(v.w, h3, l3);
            uint2 ph, pl;
            ph.x = pack_bf16(h0, h1);
            ph.y = pack_bf16(h2, h3);
            pl.x = pack_bf16(l0, l1);
            pl.y = pack_bf16(l2, l3);
            *(uint2*)(AhiS + r * PITCH + cc) = ph;
            *(uint2*)(AloS + r * PITCH + cc) = pl;
        }
    }

    int wid = tid >> 5, lane = tid & 31;
    int g = lane >> 2, tig = lane & 3;
    int wr = (wid & 3) * 32;
    int wc = (wid >> 2) * 64;

    int curMat = mat, curOsel = osel;
    const float* curBias = bias;

    for (int pass = 0; pass < 2; pass++) {
        if (pass == 1) {
            if (mat2 < 0) break;
            curMat = mat2; curOsel = osel2; curBias = bias2;
            __syncthreads();
        }
        {
            int rr = tid >> 5;
            int cc = (tid & 31) * 4;
            const __nv_bfloat16* gh = d_Bh + (size_t)curMat * 16384;
            const __nv_bfloat16* gl = d_Bl + (size_t)curMat * 16384;
            #pragma unroll 4
            for (int it = 0; it < 16; it++) {
                int n = it * 8 + rr;
                *(uint2*)(BhS + n * PITCH + cc) = *(const uint2*)(gh + n * 128 + cc);
                *(uint2*)(BlS + n * PITCH + cc) = *(const uint2*)(gl + n * 128 + cc);
            }
        }
        if (tid < 128) biasS[tid] = curBias ? curBias[tid] : 0.f;
        __syncthreads();

        float cacc[2][8][4];
        #pragma unroll
        for (int mt = 0; mt < 2; mt++)
            #pragma unroll
            for (int nt = 0; nt < 8; nt++)
                #pragma unroll
                for (int q = 0; q < 4; q++) cacc[mt][nt][q] = 0.f;

        #pragma unroll
        for (int p = 0; p < 3; p++) {
            const __nv_bfloat16* As = (p == 1) ? AloS : AhiS;
            const __nv_bfloat16* Bs = (p == 2) ? BlS : BhS;
            #pragma unroll
            for (int ks = 0; ks < 8; ks++) {
                int k0 = ks * 16;
                uint32_t af[2][4];
                #pragma unroll
                for (int mt = 0; mt < 2; mt++) {
                    const __nv_bfloat16* base = As + (wr + mt * 16) * PITCH + k0;
                    af[mt][0] = *(const uint32_t*)(base + g * PITCH + 2 * tig);
                    af[mt][1] = *(const uint32_t*)(base + (g + 8) * PITCH + 2 * tig);
                    af[mt][2] = *(const uint32_t*)(base + g * PITCH + 8 + 2 * tig);
                    af[mt][3] = *(const uint32_t*)(base + (g + 8) * PITCH + 8 + 2 * tig);
                }
                #pragma unroll
                for (int nt = 0; nt < 8; nt++) {
                    uint32_t bf[2];
                    const __nv_bfloat16* nb = Bs + (wc + nt * 8 + g) * PITCH + k0;
                    bf[0] = *(const uint32_t*)(nb + 2 * tig);
                    bf[1] = *(const uint32_t*)(nb + 8 + 2 * tig);
                    mma16816(cacc[0][nt], af[0], bf);
                    mma16816(cacc[1][nt], af[1], bf);
                }
            }
        }

        #pragma unroll
        for (int mt = 0; mt < 2; mt++) {
            int row = r0 + wr + mt * 16 + g;
            #pragma unroll
            for (int nt = 0; nt < 8; nt++) {
                int col = wc + nt * 8 + 2 * tig;
                float b0 = biasS[col], b1 = biasS[col + 1];
                float v00 = cacc[mt][nt][0] + b0, v01 = cacc[mt][nt][1] + b1;
                float v10 = cacc[mt][nt][2] + b0, v11 = cacc[mt][nt][3] + b1;
                if (curOsel == 1) {
                    if (row < NN)
                        *(float2*)(d_res0 + (size_t)row * HID + col) = make_float2(v00, v01);
                    if (row + 8 < NN)
                        *(float2*)(d_res0 + (size_t)(row + 8) * HID + col) = make_float2(v10, v11);
                } else {
                    if (row < NN)
                        *(__half2*)(d_hwh + (size_t)row * HID + col) =
                            __floats2half2_rn(v00, v01);
                    if (row + 8 < NN)
                        *(__half2*)(d_hwh + (size_t)(row + 8) * HID + col) =
                            __floats2half2_rn(v10, v11);
                }
            }
        }
    }
}

// ---------------- fused aggregate + bias + LN + residual + relu -> fp16 h ----------------
__device__ __forceinline__ void acc_edge(float4& acc, float w, uint2 raw) {
    float2 f0 = __half22float2(*(__half2*)&raw.x);
    float2 f1 = __half22float2(*(__half2*)&raw.y);
    acc.x = fmaf(w, f0.x, acc.x);
    acc.y = fmaf(w, f0.y, acc.y);
    acc.z = fmaf(w, f1.x, acc.z);
    acc.w = fmaf(w, f1.y, acc.w);
}

// rsel: -1 -> d_res0 (fp32), 0..3 -> d_hall[rsel] fp16 ; hsel: output layer index
__global__ __launch_bounds__(256) void agg_ln_k(
    const float* __restrict__ cb, const float* __restrict__ gam,
    const float* __restrict__ bet, int rsel, int hsel)
{
    int n = (blockIdx.x * 256 + threadIdx.x) >> 5;
    if (n >= NN) return;
    int lane = threadIdx.x & 31;
    const uint2* hw2 = (const uint2*)d_hwh;
    size_t loff = (size_t)lane;

    float dn = d_dis[n];
    float sn = dn * dn;
    float4 acc = ((const float4*)cb)[lane];
    acc_edge(acc, sn, hw2[(size_t)n * 32 + loff]);

    int jb = d_rowptr[n], je = d_rowptr[n + 1];
    int j = jb;
    for (; j + 4 <= je; j += 4) {
        float2 a0 = d_adj[j];
        float2 a1 = d_adj[j + 1];
        float2 a2 = d_adj[j + 2];
        float2 a3 = d_adj[j + 3];
        uint2 r0 = hw2[(size_t)__float_as_int(a0.x) * 32 + loff];
        uint2 r1 = hw2[(size_t)__float_as_int(a1.x) * 32 + loff];
        uint2 r2 = hw2[(size_t)__float_as_int(a2.x) * 32 + loff];
        uint2 r3 = hw2[(size_t)__float_as_int(a3.x) * 32 + loff];
        acc_edge(acc, a0.y, r0);
        acc_edge(acc, a1.y, r1);
        acc_edge(acc, a2.y, r2);
        acc_edge(acc, a3.y, r3);
    }
    for (; j < je; j++) {
        float2 a = d_adj[j];
        acc_edge(acc, a.y, hw2[(size_t)__float_as_int(a.x) * 32 + loff]);
    }

    float ss = acc.x + acc.y + acc.z + acc.w;
    #pragma unroll
    for (int o = 16; o > 0; o >>= 1) ss += __shfl_xor_sync(0xffffffffu, ss, o);
    float mu = ss * (1.f / 128.f);
    float dx0 = acc.x - mu, dx1 = acc.y - mu, dx2 = acc.z - mu, dx3 = acc.w - mu;
    float q = dx0 * dx0 + dx1 * dx1 + dx2 * dx2 + dx3 * dx3;
    #pragma unroll
    for (int o = 16; o > 0; o >>= 1) q += __shfl_xor_sync(0xffffffffu, q, o);
    float rstd = rsqrtf(q * (1.f / 128.f) + 1e-5f);

    float4 gv = ((const float4*)gam)[lane];
    float4 bv = ((const float4*)bet)[lane];
    float4 rv;
    if (rsel < 0) {
        rv = ((const float4*)d_res0)[(size_t)n * 32 + lane];
    } else {
        const __half* rp = d_hall + (size_t)rsel * NN * HID;
        uint2 raw = *(const uint2*)(rp + (size_t)n * HID + lane * 4);
        float2 f0 = __half22float2(*(__half2*)&raw.x);
        float2 f1 = __half22float2(*(__half2*)&raw.y);
        rv = make_float4(f0.x, f0.y, f1.x, f1.y);
    }
    float4 h;
    h.x = fmaxf(fmaf(gv.x, dx0 * rstd, bv.x) + rv.x, 0.f);
    h.y = fmaxf(fmaf(gv.y, dx1 * rstd, bv.y) + rv.y, 0.f);
    h.z = fmaxf(fmaf(gv.z, dx2 * rstd, bv.z) + rv.z, 0.f);
    h.w = fmaxf(fmaf(gv.w, dx3 * rstd, bv.w) + rv.w, 0.f);

    __half* hb = d_hall + (size_t)hsel * NN * HID;
    uint2 pk;
    *(__half2*)&pk.x = __floats2half2_rn(h.x, h.y);
    *(__half2*)&pk.y = __floats2half2_rn(h.z, h.w);
    *(uint2*)(hb + (size_t)n * HID + lane * 4) = pk;
}

// ---------------- graph segment boundaries ----------------
__global__ void mark_k(const int* __restrict__ batch) {
    int n = blockIdx.x * blockDim.x + threadIdx.x;
    if (n >= NN) return;
    int b = batch[n];
    if (n == 0 || batch[n - 1] != b) atomicMin(&d_gstart[b], n);
}

__global__ __launch_bounds__(512) void fix_k() {
    __shared__ int s[520];
    int t = threadIdx.x;
    s[t] = d_gstart[t];
    if (t == 0) s[GG] = NN;
    __syncthreads();
    for (int o = 1; o <= GG; o <<= 1) {
        int v = s[t];
        int u = (t + o <= GG) ? s[t + o] : NN;
        __syncthreads();
        s[t] = min(v, u);
        __syncthreads();
    }
    d_gstart[t] = s[t];
}

// ---------------- pooling: mean+max of (h0+h1+h2+h3)/4 over each graph ----------------
__global__ __launch_bounds__(128) void pool_k() {
    int g = blockIdx.x, c = threadIdx.x;
    int s = d_gstart[g], e = d_gstart[g + 1];
    const __half* h0 = d_hall;
    const __half* h1 = d_hall + (size_t)NN * HID;
    const __half* h2 = d_hall + 2 * (size_t)NN * HID;
    const __half* h3 = d_hall + 3 * (size_t)NN * HID;
    float sum = 0.f, mx = 0.f;
    for (int n = s; n < e; n++) {
        size_t off = (size_t)n * HID + c;
        float v = (__half2float(h0[off]) + __half2float(h1[off])
                 + __half2float(h2[off]) + __half2float(h3[off])) * 0.25f;
        sum += v;
        mx = fmaxf(mx, v);
    }
    int cnt = e - s;
    d_gmean[g * HID + c] = sum / (float)max(cnt, 1);
    d_gmaxv[g * HID + c] = mx;
}

// ---------------- head ----------------
__global__ __launch_bounds__(128) void head_k(
    const float* __restrict__ hW1, const float* __restrict__ hb1,
    const float* __restrict__ hW2, const float* __restrict__ hb2,
    float* __restrict__ out)
{
    __shared__ float gf[256];
    __shared__ float h1s[128];
    int g = blockIdx.x, t = threadIdx.x;
    gf[t] = d_gmean[g * HID + t];
    gf[128 + t] = d_gmaxv[g * HID + t];
    __syncthreads();
    float acc = hb1[t];
    #pragma unroll 8
    for (int k = 0; k < 256; k++) acc = fmaf(gf[k], hW1[k * HID + t], acc);
    h1s[t] = fmaxf(acc, 0.f);
    __syncthreads();
    if (t < NCLS) {
        float o = hb2[t];
        #pragma unroll 8
        for (int k = 0; k < 128; k++) o = fmaf(h1s[k], hW2[k * NCLS + t], o);
        out[g * NCLS + t] = o;
    }
}

// ---------------- launcher ----------------
extern "C" void kernel_launch(void* const* d_in, const int* in_sizes, int n_in,
                              void* d_out, int out_size) {
    const float* x     = (const float*)d_in[0];
    const int*   ei    = (const int*)d_in[1];
    const int*   batch = (const int*)d_in[2];
    const float* ea    = (const float*)d_in[3];
    const float* eeW1  = (const float*)d_in[4];
    const float* eeb1  = (const float*)d_in[5];
    const float* eeW2  = (const float*)d_in[6];
    const float* eeb2  = (const float*)d_in[7];
    const float* W[4]  = {(const float*)d_in[8],  (const float*)d_in[10],
                          (const float*)d_in[12], (const float*)d_in[14]};
    const float* cbp[4]= {(const float*)d_in[9],  (const float*)d_in[11],
                          (const float*)d_in[13], (const float*)d_in[15]};
    const float* gm[4] = {(const float*)d_in[16], (const float*)d_in[18],
                          (const float*)d_in[20], (const float*)d_in[22]};
    const float* be[4] = {(const float*)d_in[17], (const float*)d_in[19],
                          (const float*)d_in[21], (const float*)d_in[23]};
    const float* resW  = (const float*)d_in[24];
    const float* resB  = (const float*)d_in[25];
    const float* hW1   = (const float*)d_in[26];
    const float* hb1   = (const float*)d_in[27];
    const float* hW2   = (const float*)d_in[28];
    const float* hb2   = (const float*)d_in[29];
    float* out = (float*)d_out;

    cudaFuncSetAttribute(mma_gemm_k, cudaFuncAttributeMaxDynamicSharedMemorySize, SMEM_GEMM);

    const int nblkN = (NN + 255) / 256;
    const int nblkE = (EE + 255) / 256;
    const int tileG = (NN + 127) / 128;
    const int aggG  = (NN + 7) / 8;
    const int edgeG = EE / (128 * ETILES);

    init_k<<<nblkN, 256>>>();
    prep_e_k<<<1, 128>>>(eeW1);
    prep_k<<<5, 128>>>(resW, W[0], W[1], W[2], W[3]);
    edge_mma_k<<<edgeG, 256>>>(ea, eeb1, eeW2, eeb2, ei + EE);
    dis_k<<<nblkN, 256>>>();
    scan1_k<<<SCAN_BLOCKS, 1024>>>();
    scan2_k<<<1, 128>>>();
    scan3_k<<<SCAN_BLOCKS, 1024>>>();
    fill_k<<<nblkE, 256>>>(ei, ei + EE);

    // layer 0: fused GEMM (x@W0 -> hwh ; x@resW+resB -> res0)
    mma_gemm_k<<<tileG, 256, SMEM_GEMM>>>(x, -1, 0, 1, IN_C, nullptr, 1, 0, resB);
    agg_ln_k<<<aggG, 256>>>(cbp[0], gm[0], be[0], -1, 0);
    // layer 1
    mma_gemm_k<<<tileG, 256, SMEM_GEMM>>>(nullptr, 0, 0, 2, HID, nullptr, 0, -1, nullptr);
    agg_ln_k<<<aggG, 256>>>(cbp[1], gm[1], be[1], 0, 1);
    // layer 2
    mma_gemm_k<<<tileG, 256, SMEM_GEMM>>>(nullptr, 1, 0, 3, HID, nullptr, 0, -1, nullptr);
    agg_ln_k<<<aggG, 256>>>(cbp[2], gm[2], be[2], 1, 2);
    // layer 3
    mma_gemm_k<<<tileG, 256, SMEM_GEMM>>>(nullptr, 2, 0, 4, HID, nullptr, 0, -1, nullptr);
    agg_ln_k<<<aggG, 256>>>(cbp[3], gm[3], be[3], 2, 3);

    mark_k<<<nblkN, 256>>>(batch);
    fix_k<<<1, 512>>>();
    pool_k<<<GG, 128>>>();
    head_k<<<GG, 128>>>(hW1, hb1, hW2, hb2, out);
}

// round 16
// speedup vs baseline: 1.0572x; 1.0115x over previous
#include <cuda_runtime.h>
#include <cuda_bf16.h>
#include <cuda_fp16.h>
#include <math.h>
#include <stdint.h>

#define NN   100000
#define EE   1600000
#define GG   512
#define IN_C 96
#define HID  128
#define NCLS 100
#define SCAN_BLOCKS 98   // ceil(100000/1024)
#define ETILES 4         // edge tiles per block (512 edges) — measured best

// ---------------- scratch (device globals; no allocation) ----------------
__device__ float  d_ew[EE];
__device__ int    d_pos[EE];
__device__ int    d_cnt[NN];
__device__ int    d_rowptr[NN + 1];
__device__ int    d_bsum[SCAN_BLOCKS];
__device__ int    d_boff[SCAN_BLOCKS];
__device__ float2 d_adj[EE];            // packed (src as int bits, norm)
__device__ float  d_deg[NN];
__device__ float  d_dis[NN];
__device__ __half d_hwh[(size_t)NN * HID];        // GEMM output (gather source)
__device__ __half d_hall[4 * (size_t)NN * HID];   // per-layer hidden activations
__device__ float  d_res0[(size_t)NN * HID];
__device__ int    d_gstart[GG + 1];
__device__ float  d_gmean[GG * HID];
__device__ float  d_gmaxv[GG * HID];
// pre-split weights, n-major [128 n][128 k] bf16, hi and lo parts, 5 matrices
__device__ __nv_bfloat16 d_Bh[5 * 128 * 128];
__device__ __nv_bfloat16 d_Bl[5 * 128 * 128];
// edge-MLP W1 packed, n-major [128 n][16 k]: k0..7 = hi(W1), k8..15 = lo(W1)
__device__ __nv_bfloat16 d_EB1[128 * 16];

// ---------------- init ----------------
__global__ void init_k() {
    int i = blockIdx.x * blockDim.x + threadIdx.x;
    if (i < NN) { d_deg[i] = 1.0f; d_cnt[i] = 0; }
    if (i <= GG) d_gstart[i] = NN;
}

// ---------------- mma helpers ----------------
__device__ __forceinline__ void mma16816(float* c, const uint32_t* a, const uint32_t* b) {
    asm volatile(
        "mma.sync.aligned.m16n8k16.row.col.f32.bf16.bf16.f32 "
        "{%0,%1,%2,%3}, {%4,%5,%6,%7}, {%8,%9}, {%0,%1,%2,%3};"
        : "+f"(c[0]), "+f"(c[1]), "+f"(c[2]), "+f"(c[3])
        : "r"(a[0]), "r"(a[1]), "r"(a[2]), "r"(a[3]), "r"(b[0]), "r"(b[1]));
}

__device__ __forceinline__ void ldsm_x4(uint32_t* r, uint32_t saddr) {
    asm volatile("ldmatrix.sync.aligned.m8n8.x4.shared.b16 {%0,%1,%2,%3}, [%4];"
        : "=r"(r[0]), "=r"(r[1]), "=r"(r[2]), "=r"(r[3]) : "r"(saddr));
}

__device__ __forceinline__ void split_bf16(float v, __nv_bfloat16& h, __nv_bfloat16& l) {
    h = __float2bfloat16_rn(v);
    l = __float2bfloat16_rn(v - __bfloat162float(h));
}

__device__ __forceinline__ uint32_t pack_bf16(__nv_bfloat16 a, __nv_bfloat16 b) {
    return ((uint32_t)__bfloat16_as_ushort(b) << 16) | __bfloat16_as_ushort(a);
}

// ---------------- edge W1 prep: [Bh | Bl] packing ----------------
__global__ __launch_bounds__(128) void prep_e_k(const float* __restrict__ W1) {
    int n = threadIdx.x;
    for (int k = 0; k < 8; k++) {
        float v = W1[k * 128 + n];
        __nv_bfloat16 h, l;
        split_bf16(v, h, l);
        d_EB1[n * 16 + k] = h;
        d_EB1[n * 16 + 8 + k] = l;
    }
}

// ---------------- tensor-core edge MLP + softplus + deg/count ----------------
// Single MMA pass: A = [Ah | Ah] (fragment duplication), B = [Bh | Bl]
#define EPITCH 24
__global__ __launch_bounds__(256) void edge_mma_k(
    const float* __restrict__ ea, const float* __restrict__ b1,
    const float* __restrict__ W2, const float* __restrict__ b2v,
    const int* __restrict__ col)
{
    __shared__ __nv_bfloat16 As[128 * EPITCH];
    __shared__ __nv_bfloat16 B1s[128 * EPITCH];
    __shared__ float b1s[128];
    __shared__ float W2s[128];
    __shared__ float part[128][2];

    int tid = threadIdx.x;
    int eb = blockIdx.x * (128 * ETILES);

    if (tid < 128) { b1s[tid] = b1[tid]; W2s[tid] = W2[tid]; }

    // stage B once per block
    for (int i = tid; i < 128 * 16; i += 256) {
        int n = i >> 4, k = i & 15;
        B1s[n * EPITCH + k] = d_EB1[i];
    }
    __syncthreads();

    int wid = tid >> 5, lane = tid & 31;
    int g = lane >> 2, tig = lane & 3;
    int wr = (wid & 3) * 32;
    int wc = (wid >> 2) * 64;
    int eS = tid >> 1, half = tid & 1;

    // hoist B fragments into registers (constant across tiles)
    uint32_t b1f[8][2];
    #pragma unroll
    for (int nt = 0; nt < 8; nt++) {
        const __nv_bfloat16* nb1 = B1s + (wc + nt * 8 + g) * EPITCH;
        b1f[nt][0] = *(const uint32_t*)(nb1 + 2 * tig);
        b1f[nt][1] = *(const uint32_t*)(nb1 + 8 + 2 * tig);
    }

    for (int t = 0; t < ETILES; t++) {
        int e0 = eb + t * 128;
        // stage A tile: only hi, k0..7
        {
            float4 v = *(const float4*)(ea + (size_t)(e0 + eS) * 8 + half * 4);
            __nv_bfloat16* ah = As + eS * EPITCH + half * 4;
            ah[0] = __float2bfloat16_rn(v.x);
            ah[1] = __float2bfloat16_rn(v.y);
            ah[2] = __float2bfloat16_rn(v.z);
            ah[3] = __float2bfloat16_rn(v.w);
        }
        __syncthreads();

        // A fragments; duplicate k0..7 into the k8..15 slots
        uint32_t af[2][4];
        #pragma unroll
        for (int mt = 0; mt < 2; mt++) {
            const __nv_bfloat16* base = As + (wr + mt * 16) * EPITCH;
            af[mt][0] = *(const uint32_t*)(base + g * EPITCH + 2 * tig);
            af[mt][1] = *(const uint32_t*)(base + (g + 8) * EPITCH + 2 * tig);
            af[mt][2] = af[mt][0];
            af[mt][3] = af[mt][1];
        }

        // per-nt single-pass MMA + immediate relu·W2 consumption
        float s0[2] = {0.f, 0.f}, s8[2] = {0.f, 0.f};
        #pragma unroll
        for (int nt = 0; nt < 8; nt++) {
            float c0[4] = {0.f, 0.f, 0.f, 0.f};
            float c1[4] = {0.f, 0.f, 0.f, 0.f};
            mma16816(c0, af[0], b1f[nt]);
            mma16816(c1, af[1], b1f[nt]);
            int c = wc + nt * 8 + 2 * tig;
            float w0 = W2s[c], w1 = W2s[c + 1];
            float bb0 = b1s[c], bb1 = b1s[c + 1];
            s0[0] = fmaf(fmaxf(c0[0] + bb0, 0.f), w0, s0[0]);
            s0[0] = fmaf(fmaxf(c0[1] + bb1, 0.f), w1, s0[0]);
            s8[0] = fmaf(fmaxf(c0[2] + bb0, 0.f), w0, s8[0]);
            s8[0] = fmaf(fmaxf(c0[3] + bb1, 0.f), w1, s8[0]);
            s0[1] = fmaf(fmaxf(c1[0] + bb0, 0.f), w0, s0[1]);
            s0[1] = fmaf(fmaxf(c1[1] + bb1, 0.f), w1, s0[1]);
            s8[1] = fmaf(fmaxf(c1[2] + bb0, 0.f), w0, s8[1]);
            s8[1] = fmaf(fmaxf(c1[3] + bb1, 0.f), w1, s8[1]);
        }
        #pragma unroll
        for (int mt = 0; mt < 2; mt++) {
            float v0 = s0[mt], v8 = s8[mt];
            v0 += __shfl_xor_sync(0xffffffffu, v0, 1);
            v0 += __shfl_xor_sync(0xffffffffu, v0, 2);
            v8 += __shfl_xor_sync(0xffffffffu, v8, 1);
            v8 += __shfl_xor_sync(0xffffffffu, v8, 2);
            if (tig == 0) {
                int wn = wid >> 2;
                part[wr + mt * 16 + g][wn] = v0;
                part[wr + mt * 16 + g + 8][wn] = v8;
            }
        }
        __syncthreads();

        if (tid < 128) {
            int e = e0 + tid;
            float x = part[tid][0] + part[tid][1] + b2v[0];
            float sp = (x > 15.f) ? x : log1pf(expf(x));
            float ew = sp + 1e-4f;
            d_ew[e] = ew;
            int c = col[e];
            d_pos[e] = atomicAdd(&d_cnt[c], 1);
            atomicAdd(&d_deg[c], ew);
        }
        __syncthreads();
    }
}

__global__ void dis_k() {
    int i = blockIdx.x * blockDim.x + threadIdx.x;
    if (i < NN) d_dis[i] = rsqrtf(d_deg[i]);
}

// ---------------- hierarchical scan ----------------
__global__ __launch_bounds__(1024) void scan1_k() {
    __shared__ int wsum[32];
    int tid = threadIdx.x, lane = tid & 31, wid = tid >> 5;
    int i = blockIdx.x * 1024 + tid;
    int v = (i < NN) ? d_cnt[i] : 0;
    int s = v;
    #pragma unroll
    for (int o = 1; o < 32; o <<= 1) {
        int t = __shfl_up_sync(0xffffffffu, s, o);
        if (lane >= o) s += t;
    }
    if (lane == 31) wsum[wid] = s;
    __syncthreads();
    if (wid == 0) {
        int ws = wsum[lane];
        #pragma unroll
        for (int o = 1; o < 32; o <<= 1) {
            int t = __shfl_up_sync(0xffffffffu, ws, o);
            if (lane >= o) ws += t;
        }
        wsum[lane] = ws;
    }
    __syncthreads();
    int incl = s + ((wid > 0) ? wsum[wid - 1] : 0);
    if (i < NN) d_rowptr[i + 1] = incl;
    if (tid == 1023) d_bsum[blockIdx.x] = incl;
}

__global__ __launch_bounds__(128) void scan2_k() {
    int tid = threadIdx.x, lane = tid & 31, wid = tid >> 5;
    __shared__ int wsum[4];
    int v = (tid < SCAN_BLOCKS) ? d_bsum[tid] : 0;
    int s = v;
    #pragma unroll
    for (int o = 1; o < 32; o <<= 1) {
        int t = __shfl_up_sync(0xffffffffu, s, o);
        if (lane >= o) s += t;
    }
    if (lane == 31) wsum[wid] = s;
    __syncthreads();
    int add = 0;
    for (int w = 0; w < 4; w++) if (w < wid) add += wsum[w];
    if (tid < SCAN_BLOCKS) d_boff[tid] = s + add - v;
}

__global__ __launch_bounds__(1024) void scan3_k() {
    int i = blockIdx.x * 1024 + threadIdx.x;
    if (i < NN) d_rowptr[i + 1] += d_boff[blockIdx.x];
    if (i == 0) d_rowptr[0] = 0;
}

// ---------------- fill CSR (packed src+norm) ----------------
__global__ void fill_k(const int* __restrict__ row, const int* __restrict__ col) {
    int e = blockIdx.x * blockDim.x + threadIdx.x;
    if (e >= EE) return;
    int r = row[e], c = col[e];
    int j = d_rowptr[c] + d_pos[e];
    float2 v;
    v.x = __int_as_float(r);
    v.y = d_dis[r] * d_ew[e] * d_dis[c];
    d_adj[j] = v;
}

// ---------------- weight prep ----------------
__global__ __launch_bounds__(128) void prep_k(
    const float* __restrict__ resW, const float* __restrict__ W0,
    const float* __restrict__ W1, const float* __restrict__ W2,
    const float* __restrict__ W3)
{
    int m = blockIdx.x, n = threadIdx.x;
    const float* W; int K;
    switch (m) {
        case 0: W = resW; K = 96; break;
        case 1: W = W0;   K = 96; break;
        case 2: W = W1;   K = 128; break;
        case 3: W = W2;   K = 128; break;
        default: W = W3;  K = 128; break;
    }
    __nv_bfloat16* bh = d_Bh + (size_t)m * 16384 + (size_t)n * 128;
    __nv_bfloat16* bl = d_Bl + (size_t)m * 16384 + (size_t)n * 128;
    for (int k = 0; k < 128; k++) {
        float v = (k < K) ? W[(size_t)k * HID + n] : 0.f;
        __nv_bfloat16 h, l;
        split_bf16(v, h, l);
        bh[k] = h;
        bl[k] = l;
    }
}

// ---------------- HMMA bf16 split GEMM (ldmatrix mainloop) ----------------
#define PITCH 136
#define BUFSZ (128 * PITCH)
#define SMEM_GEMM (4 * BUFSZ * 2)

// asel: -1 -> Ain fp32 (lda cols) ; 0..3 -> d_hall[asel] fp16 (128 cols)
__global__ __launch_bounds__(256) void mma_gemm_k(
    const float* __restrict__ Ain, int asel, int osel, int mat,
    int lda, const float* __restrict__ bias,
    int osel2, int mat2, const float* __restrict__ bias2)
{
    extern __shared__ __nv_bfloat16 sm[];
    __nv_bfloat16* AhiS = sm;
    __nv_bfloat16* AloS = sm + BUFSZ;
    __nv_bfloat16* BhS  = sm + 2 * BUFSZ;
    __nv_bfloat16* BlS  = sm + 3 * BUFSZ;
    __shared__ float biasS[128];

    int tid = threadIdx.x;
    int r0 = blockIdx.x * 128;

    // stage A (fp32 or fp16 -> hi/lo bf16) once
    {
        const __half* A16 = (asel >= 0) ? (d_hall + (size_t)asel * NN * HID) : nullptr;
        int rr = tid >> 5;
        int cc = (tid & 31) * 4;
        #pragma unroll 4
        for (int it = 0; it < 16; it++) {
            int r = it * 8 + rr;
            int R = r0 + r;
            float4 v = make_float4(0.f, 0.f, 0.f, 0.f);
            if (asel >= 0) {
                if (R < NN) {
                    uint2 raw = *(const uint2*)(A16 + (size_t)R * HID + cc);
                    float2 f0 = __half22float2(*(__half2*)&raw.x);
                    float2 f1 = __half22float2(*(__half2*)&raw.y);
                    v = make_float4(f0.x, f0.y, f1.x, f1.y);
                }
            } else {
                if (R < NN && cc < lda)
                    v = *(const float4*)(Ain + (size_t)R * lda + cc);
            }
            __nv_bfloat16 h0, l0, h1, l1, h2, l2, h3, l3;
            split_bf16(v.x, h0, l0); split_bf16(v.y, h1, l1);
            split_bf16(v.z, h2, l2); split_bf16(v.w, h3, l3);
            uint2 ph, pl;
            ph.x = pack_bf16(h0, h1);
            ph.y = pack_bf16(h2, h3);
            pl.x = pack_bf16(l0, l1);
            pl.y = pack_bf16(l2, l3);
            *(uint2*)(AhiS + r * PITCH + cc) = ph;
            *(uint2*)(AloS + r * PITCH + cc) = pl;
        }
    }

    int wid = tid >> 5, lane = tid & 31;
    int g = lane >> 2, tig = lane & 3;
    int wr = (wid & 3) * 32;
    int wc = (wid >> 2) * 64;

    // ldmatrix per-lane byte offsets
    // A x4: m0..m3 = (rows 0-7,k0-7),(rows 8-15,k0-7),(rows 0-7,k8-15),(rows 8-15,k8-15)
    uint32_t aOff = (uint32_t)(((wr + (lane & 15)) * PITCH + ((lane >> 4) * 8)) * 2);
    // B x4 covering nt pair: m0,m1 = nt rows k0-7/k8-15 ; m2,m3 = nt+1 rows
    int bMat = lane >> 3;
    uint32_t bOff = (uint32_t)(((wc + (bMat >> 1) * 8 + (lane & 7)) * PITCH + (bMat & 1) * 8) * 2);

    uint32_t aHi32 = (uint32_t)__cvta_generic_to_shared(AhiS);
    uint32_t aLo32 = (uint32_t)__cvta_generic_to_shared(AloS);
    uint32_t bHi32 = (uint32_t)__cvta_generic_to_shared(BhS);
    uint32_t bLo32 = (uint32_t)__cvta_generic_to_shared(BlS);

    int curMat = mat, curOsel = osel;
    const float* curBias = bias;

    for (int pass = 0; pass < 2; pass++) {
        if (pass == 1) {
            if (mat2 < 0) break;
            curMat = mat2; curOsel = osel2; curBias = bias2;
            __syncthreads();
        }
        {
            int rr = tid >> 5;
            int cc = (tid & 31) * 4;
            const __nv_bfloat16* gh = d_Bh + (size_t)curMat * 16384;
            const __nv_bfloat16* gl = d_Bl + (size_t)curMat * 16384;
            #pragma unroll 4
            for (int it = 0; it < 16; it++) {
                int n = it * 8 + rr;
                *(uint2*)(BhS + n * PITCH + cc) = *(const uint2*)(gh + n * 128 + cc);
                *(uint2*)(BlS + n * PITCH + cc) = *(const uint2*)(gl + n * 128 + cc);
            }
        }
        if (tid < 128) biasS[tid] = curBias ? curBias[tid] : 0.f;
        __syncthreads();

        float cacc[2][8][4];
        #pragma unroll
        for (int mt = 0; mt < 2; mt++)
            #pragma unroll
            for (int nt = 0; nt < 8; nt++)
                #pragma unroll
                for (int q = 0; q < 4; q++) cacc[mt][nt][q] = 0.f;

        #pragma unroll
        for (int p = 0; p < 3; p++) {
            uint32_t aS = ((p == 1) ? aLo32 : aHi32) + aOff;
            uint32_t bS = ((p == 2) ? bLo32 : bHi32) + bOff;
            #pragma unroll
            for (int ks = 0; ks < 8; ks++) {
                uint32_t kb = (uint32_t)(ks * 32);   // 16 elems * 2B
                uint32_t af0[4], af1[4];
                ldsm_x4(af0, aS + kb);
                ldsm_x4(af1, aS + (uint32_t)(16 * PITCH * 2) + kb);
                uint32_t bfr[16];
                #pragma unroll
                for (int p2 = 0; p2 < 4; p2++)
                    ldsm_x4(bfr + 4 * p2, bS + (uint32_t)(p2 * 16 * PITCH * 2) + kb);
                #pragma unroll
                for (int nt = 0; nt < 8; nt++) {
                    mma16816(cacc[0][nt], af0, &bfr[nt * 2]);
                    mma16816(cacc[1][nt], af1, &bfr[nt * 2]);
                }
            }
        }

        #pragma unroll
        for (int mt = 0; mt < 2; mt++) {
            int row = r0 + wr + mt * 16 + g;
            #pragma unroll
            for (int nt = 0; nt < 8; nt++) {
                int col = wc + nt * 8 + 2 * tig;
                float b0 = biasS[col], b1 = biasS[col + 1];
                float v00 = cacc[mt][nt][0] + b0, v01 = cacc[mt][nt][1] + b1;
                float v10 = cacc[mt][nt][2] + b0, v11 = cacc[mt][nt][3] + b1;
                if (curOsel == 1) {
                    if (row < NN)
                        *(float2*)(d_res0 + (size_t)row * HID + col) = make_float2(v00, v01);
                    if (row + 8 < NN)
                        *(float2*)(d_res0 + (size_t)(row + 8) * HID + col) = make_float2(v10, v11);
                } else {
                    if (row < NN)
                        *(__half2*)(d_hwh + (size_t)row * HID + col) =
                            __floats2half2_rn(v00, v01);
                    if (row + 8 < NN)
                        *(__half2*)(d_hwh + (size_t)(row + 8) * HID + col) =
                            __floats2half2_rn(v10, v11);
                }
            }
        }
    }
}

// ---------------- fused aggregate + bias + LN + residual + relu -> fp16 h ----------------
__device__ __forceinline__ void acc_edge(float4& acc, float w, uint2 raw) {
    float2 f0 = __half22float2(*(__half2*)&raw.x);
    float2 f1 = __half22float2(*(__half2*)&raw.y);
    acc.x = fmaf(w, f0.x, acc.x);
    acc.y = fmaf(w, f0.y, acc.y);
    acc.z = fmaf(w, f1.x, acc.z);
    acc.w = fmaf(w, f1.y, acc.w);
}

// rsel: -1 -> d_res0 (fp32), 0..3 -> d_hall[rsel] fp16 ; hsel: output layer index
__global__ __launch_bounds__(256) void agg_ln_k(
    const float* __restrict__ cb, const float* __restrict__ gam,
    const float* __restrict__ bet, int rsel, int hsel)
{
    int n = (blockIdx.x * 256 + threadIdx.x) >> 5;
    if (n >= NN) return;
    int lane = threadIdx.x & 31;
    const uint2* hw2 = (const uint2*)d_hwh;
    size_t loff = (size_t)lane;

    float dn = d_dis[n];
    float sn = dn * dn;
    float4 acc = ((const float4*)cb)[lane];
    acc_edge(acc, sn, hw2[(size_t)n * 32 + loff]);

    int jb = d_rowptr[n], je = d_rowptr[n + 1];
    int j = jb;
    for (; j + 4 <= je; j += 4) {
        float2 a0 = d_adj[j];
        float2 a1 = d_adj[j + 1];
        float2 a2 = d_adj[j + 2];
        float2 a3 = d_adj[j + 3];
        uint2 r0 = hw2[(size_t)__float_as_int(a0.x) * 32 + loff];
        uint2 r1 = hw2[(size_t)__float_as_int(a1.x) * 32 + loff];
        uint2 r2 = hw2[(size_t)__float_as_int(a2.x) * 32 + loff];
        uint2 r3 = hw2[(size_t)__float_as_int(a3.x) * 32 + loff];
        acc_edge(acc, a0.y, r0);
        acc_edge(acc, a1.y, r1);
        acc_edge(acc, a2.y, r2);
        acc_edge(acc, a3.y, r3);
    }
    for (; j < je; j++) {
        float2 a = d_adj[j];
        acc_edge(acc, a.y, hw2[(size_t)__float_as_int(a.x) * 32 + loff]);
    }

    float ss = acc.x + acc.y + acc.z + acc.w;
    #pragma unroll
    for (int o = 16; o > 0; o >>= 1) ss += __shfl_xor_sync(0xffffffffu, ss, o);
    float mu = ss * (1.f / 128.f);
    float dx0 = acc.x - mu, dx1 = acc.y - mu, dx2 = acc.z - mu, dx3 = acc.w - mu;
    float q = dx0 * dx0 + dx1 * dx1 + dx2 * dx2 + dx3 * dx3;
    #pragma unroll
    for (int o = 16; o > 0; o >>= 1) q += __shfl_xor_sync(0xffffffffu, q, o);
    float rstd = rsqrtf(q * (1.f / 128.f) + 1e-5f);

    float4 gv = ((const float4*)gam)[lane];
    float4 bv = ((const float4*)bet)[lane];
    float4 rv;
    if (rsel < 0) {
        rv = ((const float4*)d_res0)[(size_t)n * 32 + lane];
    } else {
        const __half* rp = d_hall + (size_t)rsel * NN * HID;
        uint2 raw = *(const uint2*)(rp + (size_t)n * HID + lane * 4);
        float2 f0 = __half22float2(*(__half2*)&raw.x);
        float2 f1 = __half22float2(*(__half2*)&raw.y);
        rv = make_float4(f0.x, f0.y, f1.x, f1.y);
    }
    float4 h;
    h.x = fmaxf(fmaf(gv.x, dx0 * rstd, bv.x) + rv.x, 0.f);
    h.y = fmaxf(fmaf(gv.y, dx1 * rstd, bv.y) + rv.y, 0.f);
    h.z = fmaxf(fmaf(gv.z, dx2 * rstd, bv.z) + rv.z, 0.f);
    h.w = fmaxf(fmaf(gv.w, dx3 * rstd, bv.w) + rv.w, 0.f);

    __half* hb = d_hall + (size_t)hsel * NN * HID;
    uint2 pk;
    *(__half2*)&pk.x = __floats2half2_rn(h.x, h.y);
    *(__half2*)&pk.y = __floats2half2_rn(h.z, h.w);
    *(uint2*)(hb + (size_t)n * HID + lane * 4) = pk;
}

// ---------------- graph segment boundaries ----------------
__global__ void mark_k(const int* __restrict__ batch) {
    int n = blockIdx.x * blockDim.x + threadIdx.x;
    if (n >= NN) return;
    int b = batch[n];
    if (n == 0 || batch[n - 1] != b) atomicMin(&d_gstart[b], n);
}

__global__ __launch_bounds__(512) void fix_k() {
    __shared__ int s[520];
    int t = threadIdx.x;
    s[t] = d_gstart[t];
    if (t == 0) s[GG] = NN;
    __syncthreads();
    for (int o = 1; o <= GG; o <<= 1) {
        int v = s[t];
        int u = (t + o <= GG) ? s[t + o] : NN;
        __syncthreads();
        s[t] = min(v, u);
        __syncthreads();
    }
    d_gstart[t] = s[t];
}

// ---------------- pooling: mean+max of (h0+h1+h2+h3)/4 over each graph ----------------
__global__ __launch_bounds__(128) void pool_k() {
    int g = blockIdx.x, c = threadIdx.x;
    int s = d_gstart[g], e = d_gstart[g + 1];
    const __half* h0 = d_hall;
    const __half* h1 = d_hall + (size_t)NN * HID;
    const __half* h2 = d_hall + 2 * (size_t)NN * HID;
    const __half* h3 = d_hall + 3 * (size_t)NN * HID;
    float sum = 0.f, mx = 0.f;
    for (int n = s; n < e; n++) {
        size_t off = (size_t)n * HID + c;
        float v = (__half2float(h0[off]) + __half2float(h1[off])
                 + __half2float(h2[off]) + __half2float(h3[off])) * 0.25f;
        sum += v;
        mx = fmaxf(mx, v);
    }
    int cnt = e - s;
    d_gmean[g * HID + c] = sum / (float)max(cnt, 1);
    d_gmaxv[g * HID + c] = mx;
}

// ---------------- head ----------------
__global__ __launch_bounds__(128) void head_k(
    const float* __restrict__ hW1, const float* __restrict__ hb1,
    const float* __restrict__ hW2, const float* __restrict__ hb2,
    float* __restrict__ out)
{
    __shared__ float gf[256];
    __shared__ float h1s[128];
    int g = blockIdx.x, t = threadIdx.x;
    gf[t] = d_gmean[g * HID + t];
    gf[128 + t] = d_gmaxv[g * HID + t];
    __syncthreads();
    float acc = hb1[t];
    #pragma unroll 8
    for (int k = 0; k < 256; k++) acc = fmaf(gf[k], hW1[k * HID + t], acc);
    h1s[t] = fmaxf(acc, 0.f);
    __syncthreads();
    if (t < NCLS) {
        float o = hb2[t];
        #pragma unroll 8
        for (int k = 0; k < 128; k++) o = fmaf(h1s[k], hW2[k * NCLS + t], o);
        out[g * NCLS + t] = o;
    }
}

// ---------------- launcher ----------------
extern "C" void kernel_launch(void* const* d_in, const int* in_sizes, int n_in,
                              void* d_out, int out_size) {
    const float* x     = (const float*)d_in[0];
    const int*   ei    = (const int*)d_in[1];
    const int*   batch = (const int*)d_in[2];
    const float* ea    = (const float*)d_in[3];
    const float* eeW1  = (const float*)d_in[4];
    const float* eeb1  = (const float*)d_in[5];
    const float* eeW2  = (const float*)d_in[6];
    const float* eeb2  = (const float*)d_in[7];
    const float* W[4]  = {(const float*)d_in[8],  (const float*)d_in[10],
                          (const float*)d_in[12], (const float*)d_in[14]};
    const float* cbp[4]= {(const float*)d_in[9],  (const float*)d_in[11],
                          (const float*)d_in[13], (const float*)d_in[15]};
    const float* gm[4] = {(const float*)d_in[16], (const float*)d_in[18],
                          (const float*)d_in[20], (const float*)d_in[22]};
    const float* be[4] = {(const float*)d_in[17], (const float*)d_in[19],
                          (const float*)d_in[21], (const float*)d_in[23]};
    const float* resW  = (const float*)d_in[24];
    const float* resB  = (const float*)d_in[25];
    const float* hW1   = (const float*)d_in[26];
    const float* hb1   = (const float*)d_in[27];
    const float* hW2   = (const float*)d_in[28];
    const float* hb2   = (const float*)d_in[29];
    float* out = (float*)d_out;

    cudaFuncSetAttribute(mma_gemm_k, cudaFuncAttributeMaxDynamicSharedMemorySize, SMEM_GEMM);

    const int nblkN = (NN + 255) / 256;
    const int nblkE = (EE + 255) / 256;
    const int tileG = (NN + 127) / 128;
    const int aggG  = (NN + 7) / 8;
    const int edgeG = EE / (128 * ETILES);

    init_k<<<nblkN, 256>>>();
    prep_e_k<<<1, 128>>>(eeW1);
    prep_k<<<5, 128>>>(resW, W[0], W[1], W[2], W[3]);
    edge_mma_k<<<edgeG, 256>>>(ea, eeb1, eeW2, eeb2, ei + EE);
    dis_k<<<nblkN, 256>>>();
    scan1_k<<<SCAN_BLOCKS, 1024>>>();
    scan2_k<<<1, 128>>>();
    scan3_k<<<SCAN_BLOCKS, 1024>>>();
    fill_k<<<nblkE, 256>>>(ei, ei + EE);

    // layer 0: fused GEMM (x@W0 -> hwh ; x@resW+resB -> res0)
    mma_gemm_k<<<tileG, 256, SMEM_GEMM>>>(x, -1, 0, 1, IN_C, nullptr, 1, 0, resB);
    agg_ln_k<<<aggG, 256>>>(cbp[0], gm[0], be[0], -1, 0);
    // layer 1
    mma_gemm_k<<<tileG, 256, SMEM_GEMM>>>(nullptr, 0, 0, 2, HID, nullptr, 0, -1, nullptr);
    agg_ln_k<<<aggG, 256>>>(cbp[1], gm[1], be[1], 0, 1);
    // layer 2
    mma_gemm_k<<<tileG, 256, SMEM_GEMM>>>(nullptr, 1, 0, 3, HID, nullptr, 0, -1, nullptr);
    agg_ln_k<<<aggG, 256>>>(cbp[2], gm[2], be[2], 1, 2);
    // layer 3
    mma_gemm_k<<<tileG, 256, SMEM_GEMM>>>(nullptr, 2, 0, 4, HID, nullptr, 0, -1, nullptr);
    agg_ln_k<<<aggG, 256>>>(cbp[3], gm[3], be[3], 2, 3);

    mark_k<<<nblkN, 256>>>(batch);
    fix_k<<<1, 512>>>();
    pool_k<<<GG, 128>>>();
    head_k<<<GG, 128>>>(hW1, hb1, hW2, hb2, out);
}

// round 17
// speedup vs baseline: 1.1243x; 1.0635x over previous
#include <cuda_runtime.h>
#include <cuda_bf16.h>
#include <cuda_fp16.h>
#include <math.h>
#include <stdint.h>

#define NN   100000
#define EE   1600000
#define GG   512
#define IN_C 96
#define HID  128
#define NCLS 100
#define SCAN_BLOCKS 98   // ceil(100000/1024)
#define ETILES 4         // edge tiles per block (512 edges) — measured best

// ---------------- scratch (device globals; no allocation) ----------------
__device__ float  d_ew[EE];
__device__ int    d_pos[EE];
__device__ int    d_cnt[NN];
__device__ int    d_rowptr[NN + 1];
__device__ int    d_bsum[SCAN_BLOCKS];
__device__ int    d_boff[SCAN_BLOCKS];
__device__ float2 d_adj[EE];            // packed (src as int bits, norm)
__device__ float  d_deg[NN];
__device__ float  d_dis[NN];
__device__ __half d_hwh[(size_t)NN * HID];        // GEMM output (gather source)
__device__ __half d_hall[4 * (size_t)NN * HID];   // per-layer hidden activations
__device__ float  d_res0[(size_t)NN * HID];
__device__ int    d_gstart[GG + 1];
__device__ float  d_gmean[GG * HID];
__device__ float  d_gmaxv[GG * HID];
// pre-split weights, n-major [128 n][128 k] fp16, hi and lo parts, 5 matrices
__device__ __half d_Bh[5 * 128 * 128];
__device__ __half d_Bl[5 * 128 * 128];
// edge-MLP W1 packed bf16, n-major [128 n][16 k]: k0..7 = hi(W1), k8..15 = lo(W1)
__device__ __nv_bfloat16 d_EB1[128 * 16];

// ---------------- init ----------------
__global__ void init_k() {
    int i = blockIdx.x * blockDim.x + threadIdx.x;
    if (i < NN) { d_deg[i] = 1.0f; d_cnt[i] = 0; }
    if (i <= GG) d_gstart[i] = NN;
}

// ---------------- mma helpers ----------------
__device__ __forceinline__ void mma16816(float* c, const uint32_t* a, const uint32_t* b) {
    asm volatile(
        "mma.sync.aligned.m16n8k16.row.col.f32.bf16.bf16.f32 "
        "{%0,%1,%2,%3}, {%4,%5,%6,%7}, {%8,%9}, {%0,%1,%2,%3};"
        : "+f"(c[0]), "+f"(c[1]), "+f"(c[2]), "+f"(c[3])
        : "r"(a[0]), "r"(a[1]), "r"(a[2]), "r"(a[3]), "r"(b[0]), "r"(b[1]));
}

__device__ __forceinline__ void mma16816h(float* c, const uint32_t* a, const uint32_t* b) {
    asm volatile(
        "mma.sync.aligned.m16n8k16.row.col.f32.f16.f16.f32 "
        "{%0,%1,%2,%3}, {%4,%5,%6,%7}, {%8,%9}, {%0,%1,%2,%3};"
        : "+f"(c[0]), "+f"(c[1]), "+f"(c[2]), "+f"(c[3])
        : "r"(a[0]), "r"(a[1]), "r"(a[2]), "r"(a[3]), "r"(b[0]), "r"(b[1]));
}

__device__ __forceinline__ void ldsm_x4(uint32_t* r, uint32_t saddr) {
    asm volatile("ldmatrix.sync.aligned.m8n8.x4.shared.b16 {%0,%1,%2,%3}, [%4];"
        : "=r"(r[0]), "=r"(r[1]), "=r"(r[2]), "=r"(r[3]) : "r"(saddr));
}

__device__ __forceinline__ void split_bf16(float v, __nv_bfloat16& h, __nv_bfloat16& l) {
    h = __float2bfloat16_rn(v);
    l = __float2bfloat16_rn(v - __bfloat162float(h));
}

__device__ __forceinline__ void split_f16(float v, __half& h, __half& l) {
    h = __float2half_rn(v);
    l = __float2half_rn(v - __half2float(h));
}

__device__ __forceinline__ uint32_t pack_h16(__half a, __half b) {
    return ((uint32_t)__half_as_ushort(b) << 16) | __half_as_ushort(a);
}

// ---------------- edge W1 prep: [Bh | Bl] packing (bf16) ----------------
__global__ __launch_bounds__(128) void prep_e_k(const float* __restrict__ W1) {
    int n = threadIdx.x;
    for (int k = 0; k < 8; k++) {
        float v = W1[k * 128 + n];
        __nv_bfloat16 h, l;
        split_bf16(v, h, l);
        d_EB1[n * 16 + k] = h;
        d_EB1[n * 16 + 8 + k] = l;
    }
}

// ---------------- tensor-core edge MLP + softplus + deg/count ----------------
// Single MMA pass: A = [Ah | Ah] (fragment duplication), B = [Bh | Bl]
#define EPITCH 24
__global__ __launch_bounds__(256) void edge_mma_k(
    const float* __restrict__ ea, const float* __restrict__ b1,
    const float* __restrict__ W2, const float* __restrict__ b2v,
    const int* __restrict__ col)
{
    __shared__ __nv_bfloat16 As[128 * EPITCH];
    __shared__ __nv_bfloat16 B1s[128 * EPITCH];
    __shared__ float b1s[128];
    __shared__ float W2s[128];
    __shared__ float part[128][2];

    int tid = threadIdx.x;
    int eb = blockIdx.x * (128 * ETILES);

    if (tid < 128) { b1s[tid] = b1[tid]; W2s[tid] = W2[tid]; }

    for (int i = tid; i < 128 * 16; i += 256) {
        int n = i >> 4, k = i & 15;
        B1s[n * EPITCH + k] = d_EB1[i];
    }
    __syncthreads();

    int wid = tid >> 5, lane = tid & 31;
    int g = lane >> 2, tig = lane & 3;
    int wr = (wid & 3) * 32;
    int wc = (wid >> 2) * 64;
    int eS = tid >> 1, half = tid & 1;

    uint32_t b1f[8][2];
    #pragma unroll
    for (int nt = 0; nt < 8; nt++) {
        const __nv_bfloat16* nb1 = B1s + (wc + nt * 8 + g) * EPITCH;
        b1f[nt][0] = *(const uint32_t*)(nb1 + 2 * tig);
        b1f[nt][1] = *(const uint32_t*)(nb1 + 8 + 2 * tig);
    }

    for (int t = 0; t < ETILES; t++) {
        int e0 = eb + t * 128;
        {
            float4 v = *(const float4*)(ea + (size_t)(e0 + eS) * 8 + half * 4);
            __nv_bfloat16* ah = As + eS * EPITCH + half * 4;
            ah[0] = __float2bfloat16_rn(v.x);
            ah[1] = __float2bfloat16_rn(v.y);
            ah[2] = __float2bfloat16_rn(v.z);
            ah[3] = __float2bfloat16_rn(v.w);
        }
        __syncthreads();

        uint32_t af[2][4];
        #pragma unroll
        for (int mt = 0; mt < 2; mt++) {
            const __nv_bfloat16* base = As + (wr + mt * 16) * EPITCH;
            af[mt][0] = *(const uint32_t*)(base + g * EPITCH + 2 * tig);
            af[mt][1] = *(const uint32_t*)(base + (g + 8) * EPITCH + 2 * tig);
            af[mt][2] = af[mt][0];
            af[mt][3] = af[mt][1];
        }

        float s0[2] = {0.f, 0.f}, s8[2] = {0.f, 0.f};
        #pragma unroll
        for (int nt = 0; nt < 8; nt++) {
            float c0[4] = {0.f, 0.f, 0.f, 0.f};
            float c1[4] = {0.f, 0.f, 0.f, 0.f};
            mma16816(c0, af[0], b1f[nt]);
            mma16816(c1, af[1], b1f[nt]);
            int c = wc + nt * 8 + 2 * tig;
            float w0 = W2s[c], w1 = W2s[c + 1];
            float bb0 = b1s[c], bb1 = b1s[c + 1];
            s0[0] = fmaf(fmaxf(c0[0] + bb0, 0.f), w0, s0[0]);
            s0[0] = fmaf(fmaxf(c0[1] + bb1, 0.f), w1, s0[0]);
            s8[0] = fmaf(fmaxf(c0[2] + bb0, 0.f), w0, s8[0]);
            s8[0] = fmaf(fmaxf(c0[3] + bb1, 0.f), w1, s8[0]);
            s0[1] = fmaf(fmaxf(c1[0] + bb0, 0.f), w0, s0[1]);
            s0[1] = fmaf(fmaxf(c1[1] + bb1, 0.f), w1, s0[1]);
            s8[1] = fmaf(fmaxf(c1[2] + bb0, 0.f), w0, s8[1]);
            s8[1] = fmaf(fmaxf(c1[3] + bb1, 0.f), w1, s8[1]);
        }
        #pragma unroll
        for (int mt = 0; mt < 2; mt++) {
            float v0 = s0[mt], v8 = s8[mt];
            v0 += __shfl_xor_sync(0xffffffffu, v0, 1);
            v0 += __shfl_xor_sync(0xffffffffu, v0, 2);
            v8 += __shfl_xor_sync(0xffffffffu, v8, 1);
            v8 += __shfl_xor_sync(0xffffffffu, v8, 2);
            if (tig == 0) {
                int wn = wid >> 2;
                part[wr + mt * 16 + g][wn] = v0;
                part[wr + mt * 16 + g + 8][wn] = v8;
            }
        }
        __syncthreads();

        if (tid < 128) {
            int e = e0 + tid;
            float x = part[tid][0] + part[tid][1] + b2v[0];
            float sp = (x > 15.f) ? x : log1pf(expf(x));
            float ew = sp + 1e-4f;
            d_ew[e] = ew;
            int c = col[e];
            d_pos[e] = atomicAdd(&d_cnt[c], 1);
            atomicAdd(&d_deg[c], ew);
        }
        __syncthreads();
    }
}

__global__ void dis_k() {
    int i = blockIdx.x * blockDim.x + threadIdx.x;
    if (i < NN) d_dis[i] = rsqrtf(d_deg[i]);
}

// ---------------- hierarchical scan ----------------
__global__ __launch_bounds__(1024) void scan1_k() {
    __shared__ int wsum[32];
    int tid = threadIdx.x, lane = tid & 31, wid = tid >> 5;
    int i = blockIdx.x * 1024 + tid;
    int v = (i < NN) ? d_cnt[i] : 0;
    int s = v;
    #pragma unroll
    for (int o = 1; o < 32; o <<= 1) {
        int t = __shfl_up_sync(0xffffffffu, s, o);
        if (lane >= o) s += t;
    }
    if (lane == 31) wsum[wid] = s;
    __syncthreads();
    if (wid == 0) {
        int ws = wsum[lane];
        #pragma unroll
        for (int o = 1; o < 32; o <<= 1) {
            int t = __shfl_up_sync(0xffffffffu, ws, o);
            if (lane >= o) ws += t;
        }
        wsum[lane] = ws;
    }
    __syncthreads();
    int incl = s + ((wid > 0) ? wsum[wid - 1] : 0);
    if (i < NN) d_rowptr[i + 1] = incl;
    if (tid == 1023) d_bsum[blockIdx.x] = incl;
}

__global__ __launch_bounds__(128) void scan2_k() {
    int tid = threadIdx.x, lane = tid & 31, wid = tid >> 5;
    __shared__ int wsum[4];
    int v = (tid < SCAN_BLOCKS) ? d_bsum[tid] : 0;
    int s = v;
    #pragma unroll
    for (int o = 1; o < 32; o <<= 1) {
        int t = __shfl_up_sync(0xffffffffu, s, o);
        if (lane >= o) s += t;
    }
    if (lane == 31) wsum[wid] = s;
    __syncthreads();
    int add = 0;
    for (int w = 0; w < 4; w++) if (w < wid) add += wsum[w];
    if (tid < SCAN_BLOCKS) d_boff[tid] = s + add - v;
}

__global__ __launch_bounds__(1024) void scan3_k() {
    int i = blockIdx.x * 1024 + threadIdx.x;
    if (i < NN) d_rowptr[i + 1] += d_boff[blockIdx.x];
    if (i == 0) d_rowptr[0] = 0;
}

// ---------------- fill CSR (packed src+norm) ----------------
__global__ void fill_k(const int* __restrict__ row, const int* __restrict__ col) {
    int e = blockIdx.x * blockDim.x + threadIdx.x;
    if (e >= EE) return;
    int r = row[e], c = col[e];
    int j = d_rowptr[c] + d_pos[e];
    float2 v;
    v.x = __int_as_float(r);
    v.y = d_dis[r] * d_ew[e] * d_dis[c];
    d_adj[j] = v;
}

// ---------------- weight prep (fp16 hi/lo) ----------------
__global__ __launch_bounds__(128) void prep_k(
    const float* __restrict__ resW, const float* __restrict__ W0,
    const float* __restrict__ W1, const float* __restrict__ W2,
    const float* __restrict__ W3)
{
    int m = blockIdx.x, n = threadIdx.x;
    const float* W; int K;
    switch (m) {
        case 0: W = resW; K = 96; break;
        case 1: W = W0;   K = 96; break;
        case 2: W = W1;   K = 128; break;
        case 3: W = W2;   K = 128; break;
        default: W = W3;  K = 128; break;
    }
    __half* bh = d_Bh + (size_t)m * 16384 + (size_t)n * 128;
    __half* bl = d_Bl + (size_t)m * 16384 + (size_t)n * 128;
    for (int k = 0; k < 128; k++) {
        float v = (k < K) ? W[(size_t)k * HID + n] : 0.f;
        __half h, l;
        split_f16(v, h, l);
        bh[k] = h;
        bl[k] = l;
    }
}

// ---------------- fp16 MMA GEMM (ldmatrix mainloop) ----------------
// layers 1-3 (A fp16): 2 passes (A·Bh + A·Bl), A staged by direct copy
// layer 0   (A fp32): 3 passes (Ah·Bh + Al·Bh + Ah·Bl), A split fp16 hi/lo
#define PITCH 136
#define BUFSZ (128 * PITCH)
#define SMEM_GEMM (4 * BUFSZ * 2)

// asel: -1 -> Ain fp32 (lda cols) ; 0..3 -> d_hall[asel] fp16 (128 cols)
__global__ __launch_bounds__(256) void mma_gemm_k(
    const float* __restrict__ Ain, int asel, int osel, int mat,
    int lda, const float* __restrict__ bias,
    int osel2, int mat2, const float* __restrict__ bias2)
{
    extern __shared__ __half smh[];
    __half* AhiS = smh;
    __half* AloS = smh + BUFSZ;
    __half* BhS  = smh + 2 * BUFSZ;
    __half* BlS  = smh + 3 * BUFSZ;
    __shared__ float biasS[128];

    int tid = threadIdx.x;
    int r0 = blockIdx.x * 128;
    int npass = (asel < 0) ? 3 : 2;

    // stage A once
    {
        int rr = tid >> 5;
        int cc = (tid & 31) * 4;
        if (asel >= 0) {
            // direct fp16 copy
            const __half* A16 = d_hall + (size_t)asel * NN * HID;
            #pragma unroll 4
            for (int it = 0; it < 16; it++) {
                int r = it * 8 + rr;
                int R = r0 + r;
                uint2 raw = make_uint2(0u, 0u);
                if (R < NN) raw = *(const uint2*)(A16 + (size_t)R * HID + cc);
                *(uint2*)(AhiS + r * PITCH + cc) = raw;
            }
        } else {
            #pragma unroll 4
            for (int it = 0; it < 16; it++) {
                int r = it * 8 + rr;
                int R = r0 + r;
                float4 v = make_float4(0.f, 0.f, 0.f, 0.f);
                if (R < NN && cc < lda)
                    v = *(const float4*)(Ain + (size_t)R * lda + cc);
                __half h0, l0, h1, l1, h2, l2, h3, l3;
                split_f16(v.x, h0, l0); split_f16(v.y, h1, l1);
                split_f16(v.z, h2, l2); split_f16(v.w, h3, l3);
                uint2 ph, pl;
                ph.x = pack_h16(h0, h1);
                ph.y = pack_h16(h2, h3);
                pl.x = pack_h16(l0, l1);
                pl.y = pack_h16(l2, l3);
                *(uint2*)(AhiS + r * PITCH + cc) = ph;
                *(uint2*)(AloS + r * PITCH + cc) = pl;
            }
        }
    }

    int wid = tid >> 5, lane = tid & 31;
    int g = lane >> 2, tig = lane & 3;
    int wr = (wid & 3) * 32;
    int wc = (wid >> 2) * 64;

    // ldmatrix per-lane byte offsets
    uint32_t aOff = (uint32_t)(((wr + (lane & 15)) * PITCH + ((lane >> 4) * 8)) * 2);
    int bMat = lane >> 3;
    uint32_t bOff = (uint32_t)(((wc + (bMat >> 1) * 8 + (lane & 7)) * PITCH + (bMat & 1) * 8) * 2);

    uint32_t aHi32 = (uint32_t)__cvta_generic_to_shared(AhiS);
    uint32_t aLo32 = (uint32_t)__cvta_generic_to_shared(AloS);
    uint32_t bHi32 = (uint32_t)__cvta_generic_to_shared(BhS);
    uint32_t bLo32 = (uint32_t)__cvta_generic_to_shared(BlS);

    int curMat = mat, curOsel = osel;
    const float* curBias = bias;

    for (int pass = 0; pass < 2; pass++) {
        if (pass == 1) {
            if (mat2 < 0) break;
            curMat = mat2; curOsel = osel2; curBias = bias2;
            __syncthreads();
        }
        {
            int rr = tid >> 5;
            int cc = (tid & 31) * 4;
            const __half* gh = d_Bh + (size_t)curMat * 16384;
            const __half* gl = d_Bl + (size_t)curMat * 16384;
            #pragma unroll 4
            for (int it = 0; it < 16; it++) {
                int n = it * 8 + rr;
                *(uint2*)(BhS + n * PITCH + cc) = *(const uint2*)(gh + n * 128 + cc);
                *(uint2*)(BlS + n * PITCH + cc) = *(const uint2*)(gl + n * 128 + cc);
            }
        }
        if (tid < 128) biasS[tid] = curBias ? curBias[tid] : 0.f;
        __syncthreads();

        float cacc[2][8][4];
        #pragma unroll
        for (int mt = 0; mt < 2; mt++)
            #pragma unroll
            for (int nt = 0; nt < 8; nt++)
                #pragma unroll
                for (int q = 0; q < 4; q++) cacc[mt][nt][q] = 0.f;

        for (int p = 0; p < npass; p++) {
            // npass=3: (Ah,Bh),(Al,Bh),(Ah,Bl) ; npass=2: (A,Bh),(A,Bl)
            uint32_t aS = ((npass == 3 && p == 1) ? aLo32 : aHi32) + aOff;
            uint32_t bS = ((p == npass - 1 && p > 0) ? bLo32 : bHi32) + bOff;
            #pragma unroll
            for (int ks = 0; ks < 8; ks++) {
                uint32_t kb = (uint32_t)(ks * 32);   // 16 elems * 2B
                uint32_t af0[4], af1[4];
                ldsm_x4(af0, aS + kb);
                ldsm_x4(af1, aS + (uint32_t)(16 * PITCH * 2) + kb);
                uint32_t bfr[16];
                #pragma unroll
                for (int p2 = 0; p2 < 4; p2++)
                    ldsm_x4(bfr + 4 * p2, bS + (uint32_t)(p2 * 16 * PITCH * 2) + kb);
                #pragma unroll
                for (int nt = 0; nt < 8; nt++) {
                    mma16816h(cacc[0][nt], af0, &bfr[nt * 2]);
                    mma16816h(cacc[1][nt], af1, &bfr[nt * 2]);
                }
            }
        }

        #pragma unroll
        for (int mt = 0; mt < 2; mt++) {
            int row = r0 + wr + mt * 16 + g;
            #pragma unroll
            for (int nt = 0; nt < 8; nt++) {
                int col = wc + nt * 8 + 2 * tig;
                float b0 = biasS[col], b1 = biasS[col + 1];
                float v00 = cacc[mt][nt][0] + b0, v01 = cacc[mt][nt][1] + b1;
                float v10 = cacc[mt][nt][2] + b0, v11 = cacc[mt][nt][3] + b1;
                if (curOsel == 1) {
                    if (row < NN)
                        *(float2*)(d_res0 + (size_t)row * HID + col) = make_float2(v00, v01);
                    if (row + 8 < NN)
                        *(float2*)(d_res0 + (size_t)(row + 8) * HID + col) = make_float2(v10, v11);
                } else {
                    if (row < NN)
                        *(__half2*)(d_hwh + (size_t)row * HID + col) =
                            __floats2half2_rn(v00, v01);
                    if (row + 8 < NN)
                        *(__half2*)(d_hwh + (size_t)(row + 8) * HID + col) =
                            __floats2half2_rn(v10, v11);
                }
            }
        }
    }
}

// ---------------- fused aggregate + bias + LN + residual + relu -> fp16 h ----------------
__device__ __forceinline__ void acc_edge(float4& acc, float w, uint2 raw) {
    float2 f0 = __half22float2(*(__half2*)&raw.x);
    float2 f1 = __half22float2(*(__half2*)&raw.y);
    acc.x = fmaf(w, f0.x, acc.x);
    acc.y = fmaf(w, f0.y, acc.y);
    acc.z = fmaf(w, f1.x, acc.z);
    acc.w = fmaf(w, f1.y, acc.w);
}

// rsel: -1 -> d_res0 (fp32), 0..3 -> d_hall[rsel] fp16 ; hsel: output layer index
__global__ __launch_bounds__(256) void agg_ln_k(
    const float* __restrict__ cb, const float* __restrict__ gam,
    const float* __restrict__ bet, int rsel, int hsel)
{
    int n = (blockIdx.x * 256 + threadIdx.x) >> 5;
    if (n >= NN) return;
    int lane = threadIdx.x & 31;
    const uint2* hw2 = (const uint2*)d_hwh;
    size_t loff = (size_t)lane;

    float dn = d_dis[n];
    float sn = dn * dn;
    float4 acc = ((const float4*)cb)[lane];
    acc_edge(acc, sn, hw2[(size_t)n * 32 + loff]);

    int jb = d_rowptr[n], je = d_rowptr[n + 1];
    int j = jb;
    for (; j + 4 <= je; j += 4) {
        float2 a0 = d_adj[j];
        float2 a1 = d_adj[j + 1];
        float2 a2 = d_adj[j + 2];
        float2 a3 = d_adj[j + 3];
        uint2 r0 = hw2[(size_t)__float_as_int(a0.x) * 32 + loff];
        uint2 r1 = hw2[(size_t)__float_as_int(a1.x) * 32 + loff];
        uint2 r2 = hw2[(size_t)__float_as_int(a2.x) * 32 + loff];
        uint2 r3 = hw2[(size_t)__float_as_int(a3.x) * 32 + loff];
        acc_edge(acc, a0.y, r0);
        acc_edge(acc, a1.y, r1);
        acc_edge(acc, a2.y, r2);
        acc_edge(acc, a3.y, r3);
    }
    for (; j < je; j++) {
        float2 a = d_adj[j];
        acc_edge(acc, a.y, hw2[(size_t)__float_as_int(a.x) * 32 + loff]);
    }

    float ss = acc.x + acc.y + acc.z + acc.w;
    #pragma unroll
    for (int o = 16; o > 0; o >>= 1) ss += __shfl_xor_sync(0xffffffffu, ss, o);
    float mu = ss * (1.f / 128.f);
    float dx0 = acc.x - mu, dx1 = acc.y - mu, dx2 = acc.z - mu, dx3 = acc.w - mu;
    float q = dx0 * dx0 + dx1 * dx1 + dx2 * dx2 + dx3 * dx3;
    #pragma unroll
    for (int o = 16; o > 0; o >>= 1) q += __shfl_xor_sync(0xffffffffu, q, o);
    float rstd = rsqrtf(q * (1.f / 128.f) + 1e-5f);

    float4 gv = ((const float4*)gam)[lane];
    float4 bv = ((const float4*)bet)[lane];
    float4 rv;
    if (rsel < 0) {
        rv = ((const float4*)d_res0)[(size_t)n * 32 + lane];
    } else {
        const __half* rp = d_hall + (size_t)rsel * NN * HID;
        uint2 raw = *(const uint2*)(rp + (size_t)n * HID + lane * 4);
        float2 f0 = __half22float2(*(__half2*)&raw.x);
        float2 f1 = __half22float2(*(__half2*)&raw.y);
        rv = make_float4(f0.x, f0.y, f1.x, f1.y);
    }
    float4 h;
    h.x = fmaxf(fmaf(gv.x, dx0 * rstd, bv.x) + rv.x, 0.f);
    h.y = fmaxf(fmaf(gv.y, dx1 * rstd, bv.y) + rv.y, 0.f);
    h.z = fmaxf(fmaf(gv.z, dx2 * rstd, bv.z) + rv.z, 0.f);
    h.w = fmaxf(fmaf(gv.w, dx3 * rstd, bv.w) + rv.w, 0.f);

    __half* hb = d_hall + (size_t)hsel * NN * HID;
    uint2 pk;
    *(__half2*)&pk.x = __floats2half2_rn(h.x, h.y);
    *(__half2*)&pk.y = __floats2half2_rn(h.z, h.w);
    *(uint2*)(hb + (size_t)n * HID + lane * 4) = pk;
}

// ---------------- graph segment boundaries ----------------
__global__ void mark_k(const int* __restrict__ batch) {
    int n = blockIdx.x * blockDim.x + threadIdx.x;
    if (n >= NN) return;
    int b = batch[n];
    if (n == 0 || batch[n - 1] != b) atomicMin(&d_gstart[b], n);
}

__global__ __launch_bounds__(512) void fix_k() {
    __shared__ int s[520];
    int t = threadIdx.x;
    s[t] = d_gstart[t];
    if (t == 0) s[GG] = NN;
    __syncthreads();
    for (int o = 1; o <= GG; o <<= 1) {
        int v = s[t];
        int u = (t + o <= GG) ? s[t + o] : NN;
        __syncthreads();
        s[t] = min(v, u);
        __syncthreads();
    }
    d_gstart[t] = s[t];
}

// ---------------- pooling: mean+max of (h0+h1+h2+h3)/4 over each graph ----------------
__global__ __launch_bounds__(128) void pool_k() {
    int g = blockIdx.x, c = threadIdx.x;
    int s = d_gstart[g], e = d_gstart[g + 1];
    const __half* h0 = d_hall;
    const __half* h1 = d_hall + (size_t)NN * HID;
    const __half* h2 = d_hall + 2 * (size_t)NN * HID;
    const __half* h3 = d_hall + 3 * (size_t)NN * HID;
    float sum = 0.f, mx = 0.f;
    for (int n = s; n < e; n++) {
        size_t off = (size_t)n * HID + c;
        float v = (__half2float(h0[off]) + __half2float(h1[off])
                 + __half2float(h2[off]) + __half2float(h3[off])) * 0.25f;
        sum += v;
        mx = fmaxf(mx, v);
    }
    int cnt = e - s;
    d_gmean[g * HID + c] = sum / (float)max(cnt, 1);
    d_gmaxv[g * HID + c] = mx;
}

// ---------------- head ----------------
__global__ __launch_bounds__(128) void head_k(
    const float* __restrict__ hW1, const float* __restrict__ hb1,
    const float* __restrict__ hW2, const float* __restrict__ hb2,
    float* __restrict__ out)
{
    __shared__ float gf[256];
    __shared__ float h1s[128];
    int g = blockIdx.x, t = threadIdx.x;
    gf[t] = d_gmean[g * HID + t];
    gf[128 + t] = d_gmaxv[g * HID + t];
    __syncthreads();
    float acc = hb1[t];
    #pragma unroll 8
    for (int k = 0; k < 256; k++) acc = fmaf(gf[k], hW1[k * HID + t], acc);
    h1s[t] = fmaxf(acc, 0.f);
    __syncthreads();
    if (t < NCLS) {
        float o = hb2[t];
        #pragma unroll 8
        for (int k = 0; k < 128; k++) o = fmaf(h1s[k], hW2[k * NCLS + t], o);
        out[g * NCLS + t] = o;
    }
}

// ---------------- launcher ----------------
extern "C" void kernel_launch(void* const* d_in, const int* in_sizes, int n_in,
                              void* d_out, int out_size) {
    const float* x     = (const float*)d_in[0];
    const int*   ei    = (const int*)d_in[1];
    const int*   batch = (const int*)d_in[2];
    const float* ea    = (const float*)d_in[3];
    const float* eeW1  = (const float*)d_in[4];
    const float* eeb1  = (const float*)d_in[5];
    const float* eeW2  = (const float*)d_in[6];
    const float* eeb2  = (const float*)d_in[7];
    const float* W[4]  = {(const float*)d_in[8],  (const float*)d_in[10],
                          (const float*)d_in[12], (const float*)d_in[14]};
    const float* cbp[4]= {(const float*)d_in[9],  (const float*)d_in[11],
                          (const float*)d_in[13], (const float*)d_in[15]};
    const float* gm[4] = {(const float*)d_in[16], (const float*)d_in[18],
                          (const float*)d_in[20], (const float*)d_in[22]};
    const float* be[4] = {(const float*)d_in[17], (const float*)d_in[19],
                          (const float*)d_in[21], (const float*)d_in[23]};
    const float* resW  = (const float*)d_in[24];
    const float* resB  = (const float*)d_in[25];
    const float* hW1   = (const float*)d_in[26];
    const float* hb1   = (const float*)d_in[27];
    const float* hW2   = (const float*)d_in[28];
    const float* hb2   = (const float*)d_in[29];
    float* out = (float*)d_out;

    cudaFuncSetAttribute(mma_gemm_k, cudaFuncAttributeMaxDynamicSharedMemorySize, SMEM_GEMM);

    const int nblkN = (NN + 255) / 256;
    const int nblkE = (EE + 255) / 256;
    const int tileG = (NN + 127) / 128;
    const int aggG  = (NN + 7) / 8;
    const int edgeG = EE / (128 * ETILES);

    init_k<<<nblkN, 256>>>();
    prep_e_k<<<1, 128>>>(eeW1);
    prep_k<<<5, 128>>>(resW, W[0], W[1], W[2], W[3]);
    edge_mma_k<<<edgeG, 256>>>(ea, eeb1, eeW2, eeb2, ei + EE);
    dis_k<<<nblkN, 256>>>();
    scan1_k<<<SCAN_BLOCKS, 1024>>>();
    scan2_k<<<1, 128>>>();
    scan3_k<<<SCAN_BLOCKS, 1024>>>();
    fill_k<<<nblkE, 256>>>(ei, ei + EE);

    // layer 0: fused GEMM (x@W0 -> hwh ; x@resW+resB -> res0), 3-pass fp16-split A
    mma_gemm_k<<<tileG, 256, SMEM_GEMM>>>(x, -1, 0, 1, IN_C, nullptr, 1, 0, resB);
    agg_ln_k<<<aggG, 256>>>(cbp[0], gm[0], be[0], -1, 0);
    // layer 1 (A fp16, 2-pass)
    mma_gemm_k<<<tileG, 256, SMEM_GEMM>>>(nullptr, 0, 0, 2, HID, nullptr, 0, -1, nullptr);
    agg_ln_k<<<aggG, 256>>>(cbp[1], gm[1], be[1], 0, 1);
    // layer 2
    mma_gemm_k<<<tileG, 256, SMEM_GEMM>>>(nullptr, 1, 0, 3, HID, nullptr, 0, -1, nullptr);
    agg_ln_k<<<aggG, 256>>>(cbp[2], gm[2], be[2], 1, 2);
    // layer 3
    mma_gemm_k<<<tileG, 256, SMEM_GEMM>>>(nullptr, 2, 0, 4, HID, nullptr, 0, -1, nullptr);
    agg_ln_k<<<aggG, 256>>>(cbp[3], gm[3], be[3], 2, 3);

    mark_k<<<nblkN, 256>>>(batch);
    fix_k<<<1, 512>>>();
    pool_k<<<GG, 128>>>();
    head_k<<<GG, 128>>>(hW1, hb1, hW2, hb2, out);
}